// round 3
// baseline (speedup 1.0000x reference)
#include <cuda_runtime.h>
#include <cuda_bf16.h>
#include <cstdint>
#include <cstddef>

// ============================================================================
// Problem: B=8, Lq=Lk=2048, D=768
//   q = queries@Wq^T+bq ; v = values@Wv^T+bv ; k = v@Wk^T+bk
//   attn = sigmoid(mask ? q@k^T : -1e9) ; out = attn@v
//
// Target is plain sm_100 (no 'a' features): tcgen05 unavailable. Use the base
// ISA tensor path: mma.sync.m16n8k16 bf16 + ldmatrix + cp.async.
// Precision: every operand split into bf16 hi/lo; 3 products hh+hl+lh into
// fp32 accumulators (error ~2^-18 per term).
// ============================================================================

#define LQn 2048
#define LKn 2048
#define Dn  768
#define Bn  8
#define MR  (Bn * LQn)          // 16384

typedef __nv_bfloat16 bf16;
typedef __nv_bfloat162 bf162;

// ---------------- static device scratch (no cudaMalloc allowed) -------------
static __device__ bf16 g_qin_h[(size_t)MR * Dn], g_qin_l[(size_t)MR * Dn];
static __device__ bf16 g_vin_h[(size_t)MR * Dn], g_vin_l[(size_t)MR * Dn];
static __device__ bf16 g_wq_h[(size_t)Dn * Dn],  g_wq_l[(size_t)Dn * Dn];
static __device__ bf16 g_wk_h[(size_t)Dn * Dn],  g_wk_l[(size_t)Dn * Dn];
static __device__ bf16 g_wv_h[(size_t)Dn * Dn],  g_wv_l[(size_t)Dn * Dn];
static __device__ bf16 g_q_h[(size_t)MR * Dn],   g_q_l[(size_t)MR * Dn];
static __device__ bf16 g_k_h[(size_t)MR * Dn],   g_k_l[(size_t)MR * Dn];
static __device__ bf16 g_v_h[(size_t)MR * Dn],   g_v_l[(size_t)MR * Dn];
static __device__ bf16 g_at_h[(size_t)Bn * LQn * LKn];
static __device__ bf16 g_at_l[(size_t)Bn * LQn * LKn];
static __device__ int  g_mask_mode;   // 0=byte, 1=int32, 2=float32

// ---------------- PTX helpers ------------------------------------------------
__device__ __forceinline__ uint32_t smem_u32(const void* p) {
    uint32_t a;
    asm("{ .reg .u64 t; cvta.to.shared.u64 t, %1; cvt.u32.u64 %0, t; }"
        : "=r"(a) : "l"(p));
    return a;
}

__device__ __forceinline__ void cpa16(uint32_t s, const void* g) {
    asm volatile("cp.async.cg.shared.global [%0], [%1], 16;"
                 :: "r"(s), "l"(g) : "memory");
}
#define CP_COMMIT() asm volatile("cp.async.commit_group;" ::: "memory")
#define CP_WAIT2()  asm volatile("cp.async.wait_group 2;"  ::: "memory")

__device__ __forceinline__ void ldsm4(uint32_t* r, uint32_t a) {
    asm volatile("ldmatrix.sync.aligned.m8n8.x4.shared.b16 {%0,%1,%2,%3}, [%4];"
                 : "=r"(r[0]), "=r"(r[1]), "=r"(r[2]), "=r"(r[3]) : "r"(a));
}
__device__ __forceinline__ void ldsm4t(uint32_t* r, uint32_t a) {
    asm volatile("ldmatrix.sync.aligned.m8n8.x4.trans.shared.b16 {%0,%1,%2,%3}, [%4];"
                 : "=r"(r[0]), "=r"(r[1]), "=r"(r[2]), "=r"(r[3]) : "r"(a));
}
__device__ __forceinline__ void mma16816(float* c, const uint32_t* a, const uint32_t* b) {
    asm volatile(
        "mma.sync.aligned.m16n8k16.row.col.f32.bf16.bf16.f32 "
        "{%0,%1,%2,%3}, {%4,%5,%6,%7}, {%8,%9}, {%0,%1,%2,%3};"
        : "+f"(c[0]), "+f"(c[1]), "+f"(c[2]), "+f"(c[3])
        : "r"(a[0]), "r"(a[1]), "r"(a[2]), "r"(a[3]), "r"(b[0]), "r"(b[1]));
}

__device__ __forceinline__ float sigf(float x) {
    return 1.0f / (1.0f + __expf(-x));
}

// ---------------- small kernels ----------------------------------------------
__global__ void detect_mask_kernel(const unsigned* __restrict__ w, int n) {
    int anyF = 0, anyO = 0;
    for (int i = threadIdx.x; i < n; i += blockDim.x) {
        unsigned x = w[i];
        anyF |= (x == 0x3F800000u);
        anyO |= (x != 0u && x != 1u && x != 0x3F800000u);
    }
    anyF = __syncthreads_or(anyF);
    anyO = __syncthreads_or(anyO);
    if (threadIdx.x == 0) g_mask_mode = anyF ? 2 : (anyO ? 0 : 1);
}

// split fp32 -> bf16 hi/lo planes (n multiple of 4)
__global__ void split_kernel(const float* __restrict__ s,
                             bf16* __restrict__ h, bf16* __restrict__ l, int n4) {
    int i = blockIdx.x * blockDim.x + threadIdx.x;
    if (i >= n4) return;
    float4 x = reinterpret_cast<const float4*>(s)[i];
    bf16 h0 = __float2bfloat16_rn(x.x), h1 = __float2bfloat16_rn(x.y);
    bf16 h2 = __float2bfloat16_rn(x.z), h3 = __float2bfloat16_rn(x.w);
    bf162 hh0; hh0.x = h0; hh0.y = h1;
    bf162 hh1; hh1.x = h2; hh1.y = h3;
    bf162 ll0, ll1;
    ll0.x = __float2bfloat16_rn(x.x - __bfloat162float(h0));
    ll0.y = __float2bfloat16_rn(x.y - __bfloat162float(h1));
    ll1.x = __float2bfloat16_rn(x.z - __bfloat162float(h2));
    ll1.y = __float2bfloat16_rn(x.w - __bfloat162float(h3));
    reinterpret_cast<bf162*>(h)[i * 2 + 0] = hh0;
    reinterpret_cast<bf162*>(h)[i * 2 + 1] = hh1;
    reinterpret_cast<bf162*>(l)[i * 2 + 0] = ll0;
    reinterpret_cast<bf162*>(l)[i * 2 + 1] = ll1;
}

// ---------------- GEMM --------------------------------------------------------
// CTA tile 128x128, BK=32, 8 warps (warp tile 32x64), 3-stage cp.async.
// A: [M, lda] row-major hi/lo planes. B:
//   BTRANS=false: [N, ldb] row-major (NT; ldmatrix non-trans)
//   BTRANS=true : [K, ldb] row-major (NN; ldmatrix trans)
// EPI: 0 = +bias, split-store bf16 hi/lo | 1 = mask+sigmoid, split-store |
//      2 = plain fp32 store.
// Stage layout (32 KB): Ah@0 Al@8K Bh@16K Bl@24K.
//   A-type tiles: 128 rows x 32 k bf16, 64 B/row; seg c in [0,4):
//     addr = r*64 + (c ^ ((r>>1)&3))*16
//   B NN tile: 32 k x 128 n, 256 B/row; seg ns in [0,16):
//     addr = k*256 + (ns ^ (k&7))*16

template<int EPI, bool BTRANS>
__global__ void __launch_bounds__(256, 1)
gemm_bf16(const bf16* __restrict__ Ah, const bf16* __restrict__ Al,
          const bf16* __restrict__ Bh, const bf16* __restrict__ Bl,
          bf16* __restrict__ Oh, bf16* __restrict__ Ol,
          float* __restrict__ Of,
          const float* __restrict__ bias, const void* __restrict__ mask,
          int lda, int ldb, int ldo, int K,
          long sA, long sB, long sO)
{
    extern __shared__ char smem[];
    const uint32_t sm0 = smem_u32(smem);

    const int tid  = threadIdx.x;
    const int z    = blockIdx.z;
    const int mbase = blockIdx.y * 128;
    const int nbase = blockIdx.x * 128;

    Ah += (size_t)z * sA;  Al += (size_t)z * sA;
    Bh += (size_t)z * sB;  Bl += (size_t)z * sB;

    const int warp = tid >> 5;
    const int lane = tid & 31;
    const int wm = warp >> 1;          // 0..3 -> rows wm*32
    const int wn = warp & 1;           // 0..1 -> cols wn*64
    const int m8 = lane >> 3;          // ldmatrix matrix idx
    const int l8 = lane & 7;

    const int C = K >> 5;

    // ---- fill helpers ----
    auto issue = [&](int c) {
        const int s = c - (c / 3) * 3;
        const uint32_t sb = sm0 + (uint32_t)s * 32768u;
        const size_t ka = (size_t)c * 32;
        // A hi/lo
        {
            const bf16* gh = Ah + (size_t)mbase * lda + ka;
            const bf16* gl = Al + (size_t)mbase * lda + ka;
#pragma unroll
            for (int i = 0; i < 2; ++i) {
                int seg = tid + i * 256;          // 0..511
                int r = seg >> 2, cc = seg & 3;
                uint32_t sa = sb + r * 64 + ((cc ^ ((r >> 1) & 3)) << 4);
                cpa16(sa,        gh + (size_t)r * lda + cc * 8);
                cpa16(sa + 8192, gl + (size_t)r * lda + cc * 8);
            }
        }
        if (!BTRANS) {
            const bf16* gh = Bh + (size_t)nbase * ldb + ka;
            const bf16* gl = Bl + (size_t)nbase * ldb + ka;
#pragma unroll
            for (int i = 0; i < 2; ++i) {
                int seg = tid + i * 256;
                int r = seg >> 2, cc = seg & 3;
                uint32_t sa = sb + 16384 + r * 64 + ((cc ^ ((r >> 1) & 3)) << 4);
                cpa16(sa,        gh + (size_t)r * ldb + cc * 8);
                cpa16(sa + 8192, gl + (size_t)r * ldb + cc * 8);
            }
        } else {
            const bf16* gh = Bh + ka * ldb + nbase;
            const bf16* gl = Bl + ka * ldb + nbase;
#pragma unroll
            for (int i = 0; i < 2; ++i) {
                int seg = tid + i * 256;
                int k = seg >> 4, ns = seg & 15;
                uint32_t sa = sb + 16384 + k * 256 + ((ns ^ (k & 7)) << 4);
                cpa16(sa,        gh + (size_t)k * ldb + ns * 8);
                cpa16(sa + 8192, gl + (size_t)k * ldb + ns * 8);
            }
        }
    };

    issue(0); CP_COMMIT();
    issue(1); CP_COMMIT();
    issue(2); CP_COMMIT();

    float acc[2][8][4];
#pragma unroll
    for (int a = 0; a < 2; ++a)
#pragma unroll
        for (int b = 0; b < 8; ++b)
#pragma unroll
            for (int d = 0; d < 4; ++d) acc[a][b][d] = 0.0f;

    for (int c = 0; c < C; ++c) {
        CP_WAIT2();
        __syncthreads();

        const int s = c - (c / 3) * 3;
        const uint32_t sb = sm0 + (uint32_t)s * 32768u;

#pragma unroll
        for (int ks = 0; ks < 2; ++ks) {
            uint32_t ahf[2][4], alf[2][4];
#pragma unroll
            for (int mt = 0; mt < 2; ++mt) {
                int r = wm * 32 + mt * 16 + (m8 & 1) * 8 + l8;
                int cA = 2 * ks + (m8 >> 1);
                uint32_t off = r * 64 + ((cA ^ ((r >> 1) & 3)) << 4);
                ldsm4(ahf[mt], sb + off);
                ldsm4(alf[mt], sb + 8192 + off);
            }
            uint32_t bhf[4][4], blf[4][4];
            if (!BTRANS) {
#pragma unroll
                for (int g = 0; g < 4; ++g) {
                    int n = wn * 64 + g * 16 + (m8 >> 1) * 8 + l8;
                    int cB = 2 * ks + (m8 & 1);
                    uint32_t off = n * 64 + ((cB ^ ((n >> 1) & 3)) << 4);
                    ldsm4(bhf[g], sb + 16384 + off);
                    ldsm4(blf[g], sb + 24576 + off);
                }
            } else {
#pragma unroll
                for (int g = 0; g < 4; ++g) {
                    int k = ks * 16 + (m8 & 1) * 8 + l8;
                    int ns = ((wn * 64 + g * 16) >> 3) + (m8 >> 1);
                    uint32_t off = k * 256 + ((ns ^ (k & 7)) << 4);
                    ldsm4t(bhf[g], sb + 16384 + off);
                    ldsm4t(blf[g], sb + 24576 + off);
                }
            }
#pragma unroll
            for (int mt = 0; mt < 2; ++mt)
#pragma unroll
                for (int nt = 0; nt < 8; ++nt) {
                    const uint32_t* bH = &bhf[nt >> 1][(nt & 1) * 2];
                    const uint32_t* bL = &blf[nt >> 1][(nt & 1) * 2];
                    mma16816(acc[mt][nt], ahf[mt], bH);
                    mma16816(acc[mt][nt], ahf[mt], bL);
                    mma16816(acc[mt][nt], alf[mt], bH);
                }
        }

        __syncthreads();
        if (c + 3 < C) issue(c + 3);
        CP_COMMIT();
    }

    // ---------------- epilogue ------------------------------------------------
    const int rb = mbase + wm * 32 + (lane >> 2);
    const int cb = nbase + wn * 64 + (lane & 3) * 2;
    const int mode = (EPI == 1) ? g_mask_mode : 0;

    if (EPI == 0) { Oh += (size_t)z * sO; Ol += (size_t)z * sO; }
    if (EPI == 1) { Oh += (size_t)z * sO; Ol += (size_t)z * sO; }
    if (EPI == 2) { Of += (size_t)z * sO; }

#pragma unroll
    for (int mt = 0; mt < 2; ++mt)
#pragma unroll
        for (int h = 0; h < 1 + 1; ++h) {
            const int gr = rb + mt * 16 + h * 8;
#pragma unroll
            for (int nt = 0; nt < 8; ++nt) {
                const int gc = cb + nt * 8;
                float x0 = acc[mt][nt][h * 2 + 0];
                float x1 = acc[mt][nt][h * 2 + 1];

                if (EPI == 0) {
                    x0 += bias[gc];
                    x1 += bias[gc + 1];
                } else if (EPI == 1) {
                    int f0, f1;
                    const size_t mo = (size_t)z * ((size_t)LQn * LKn)
                                    + (size_t)gr * LKn + gc;
                    if (mode == 0) {
                        const unsigned char* mp = (const unsigned char*)mask + mo;
                        f0 = mp[0]; f1 = mp[1];
                    } else if (mode == 1) {
                        const int* mp = (const int*)mask + mo;
                        f0 = mp[0]; f1 = mp[1];
                    } else {
                        const float* mp = (const float*)mask + mo;
                        f0 = (mp[0] != 0.0f); f1 = (mp[1] != 0.0f);
                    }
                    x0 = f0 ? sigf(x0) : 0.0f;
                    x1 = f1 ? sigf(x1) : 0.0f;
                }

                if (EPI == 2) {
                    float2 p; p.x = x0; p.y = x1;
                    *reinterpret_cast<float2*>(Of + (size_t)gr * ldo + gc) = p;
                } else {
                    bf162 ph, pl;
                    ph.x = __float2bfloat16_rn(x0);
                    ph.y = __float2bfloat16_rn(x1);
                    pl.x = __float2bfloat16_rn(x0 - __bfloat162float(ph.x));
                    pl.y = __float2bfloat16_rn(x1 - __bfloat162float(ph.y));
                    *reinterpret_cast<bf162*>(Oh + (size_t)gr * ldo + gc) = ph;
                    *reinterpret_cast<bf162*>(Ol + (size_t)gr * ldo + gc) = pl;
                }
            }
        }
}

// ---------------- host side ---------------------------------------------------
extern "C" void kernel_launch(void* const* d_in, const int* in_sizes, int n_in,
                              void* d_out, int out_size)
{
    const float* queries = (const float*)d_in[0];
    const float* values  = (const float*)d_in[1];
    const void*  mask    = d_in[2];
    const float* Wq = (const float*)d_in[3];
    const float* bq = (const float*)d_in[4];
    const float* Wk = (const float*)d_in[5];
    const float* bk = (const float*)d_in[6];
    const float* Wv = (const float*)d_in[7];
    const float* bv = (const float*)d_in[8];
    float* out = (float*)d_out;

    bf16 *qin_h, *qin_l, *vin_h, *vin_l;
    bf16 *wq_h, *wq_l, *wk_h, *wk_l, *wv_h, *wv_l;
    bf16 *q_h, *q_l, *k_h, *k_l, *v_h, *v_l, *at_h, *at_l;
    cudaGetSymbolAddress((void**)&qin_h, g_qin_h);
    cudaGetSymbolAddress((void**)&qin_l, g_qin_l);
    cudaGetSymbolAddress((void**)&vin_h, g_vin_h);
    cudaGetSymbolAddress((void**)&vin_l, g_vin_l);
    cudaGetSymbolAddress((void**)&wq_h, g_wq_h);
    cudaGetSymbolAddress((void**)&wq_l, g_wq_l);
    cudaGetSymbolAddress((void**)&wk_h, g_wk_h);
    cudaGetSymbolAddress((void**)&wk_l, g_wk_l);
    cudaGetSymbolAddress((void**)&wv_h, g_wv_h);
    cudaGetSymbolAddress((void**)&wv_l, g_wv_l);
    cudaGetSymbolAddress((void**)&q_h, g_q_h);
    cudaGetSymbolAddress((void**)&q_l, g_q_l);
    cudaGetSymbolAddress((void**)&k_h, g_k_h);
    cudaGetSymbolAddress((void**)&k_l, g_k_l);
    cudaGetSymbolAddress((void**)&v_h, g_v_h);
    cudaGetSymbolAddress((void**)&v_l, g_v_l);
    cudaGetSymbolAddress((void**)&at_h, g_at_h);
    cudaGetSymbolAddress((void**)&at_l, g_at_l);

    constexpr int SMEM = 3 * 32768;   // 96 KB
    static int attr_done = 0;
    if (!attr_done) {
        cudaFuncSetAttribute(gemm_bf16<0, false>,
                             cudaFuncAttributeMaxDynamicSharedMemorySize, SMEM);
        cudaFuncSetAttribute(gemm_bf16<1, false>,
                             cudaFuncAttributeMaxDynamicSharedMemorySize, SMEM);
        cudaFuncSetAttribute(gemm_bf16<2, true>,
                             cudaFuncAttributeMaxDynamicSharedMemorySize, SMEM);
        attr_done = 1;
    }

    // mask dtype detection (scan first 32 KB of words)
    detect_mask_kernel<<<1, 256>>>((const unsigned*)mask, 8192);

    // input splits
    {
        int n4 = MR * Dn / 4;               // 3,145,728
        split_kernel<<<(n4 + 255) / 256, 256>>>(queries, qin_h, qin_l, n4);
        split_kernel<<<(n4 + 255) / 256, 256>>>(values,  vin_h, vin_l, n4);
        int w4 = Dn * Dn / 4;               // 147,456
        split_kernel<<<(w4 + 255) / 256, 256>>>(Wq, wq_h, wq_l, w4);
        split_kernel<<<(w4 + 255) / 256, 256>>>(Wk, wk_h, wk_l, w4);
        split_kernel<<<(w4 + 255) / 256, 256>>>(Wv, wv_h, wv_l, w4);
    }

    // q = queries @ Wq^T + bq  -> q planes
    gemm_bf16<0, false><<<dim3(6, 128, 1), 256, SMEM>>>(
        qin_h, qin_l, wq_h, wq_l, q_h, q_l, nullptr, bq, nullptr,
        Dn, Dn, Dn, Dn, 0, 0, 0);
    // v = values @ Wv^T + bv  -> v planes
    gemm_bf16<0, false><<<dim3(6, 128, 1), 256, SMEM>>>(
        vin_h, vin_l, wv_h, wv_l, v_h, v_l, nullptr, bv, nullptr,
        Dn, Dn, Dn, Dn, 0, 0, 0);
    // k = v @ Wk^T + bk  -> k planes (input is the split v)
    gemm_bf16<0, false><<<dim3(6, 128, 1), 256, SMEM>>>(
        v_h, v_l, wk_h, wk_l, k_h, k_l, nullptr, bk, nullptr,
        Dn, Dn, Dn, Dn, 0, 0, 0);
    // attn = sigmoid(mask ? q@k^T : -1e9)  -> attn planes, per batch
    gemm_bf16<1, false><<<dim3(16, 16, Bn), 256, SMEM>>>(
        q_h, q_l, k_h, k_l, at_h, at_l, nullptr, nullptr, mask,
        Dn, Dn, LKn, Dn,
        (long)LQn * Dn, (long)LKn * Dn, (long)LQn * LKn);
    // out = attn @ v  (NN: B = v [K=l, N=d] row-major), per batch
    gemm_bf16<2, true><<<dim3(6, 16, Bn), 256, SMEM>>>(
        at_h, at_l, v_h, v_l, nullptr, nullptr, out, nullptr, nullptr,
        LKn, Dn, Dn, LKn,
        (long)LQn * LKn, (long)LKn * Dn, (long)LQn * Dn);
}

// round 4
// speedup vs baseline: 1.4136x; 1.4136x over previous
#include <cuda_runtime.h>
#include <cuda_fp16.h>
#include <cstdint>
#include <cstddef>

// ============================================================================
// Problem: B=8, Lq=Lk=2048, D=768
//   q = queries@Wq^T+bq ; v = values@Wv^T+bv ; k = v@Wk^T+bk
//   attn = sigmoid(mask ? q@k^T : -1e9) ; out = attn@v
//
// Plain sm_100 target (no tcgen05). Base-ISA tensor path:
// mma.sync.m16n8k16.f32.f16.f16.f32 + ldmatrix + cp.async.
// Precision: fp16 hi/lo planes. Projections & score: 3 products (hh+hl+lh,
// residual ~2^-24). Context: attn stored single fp16, v hi/lo pair ->
// 2 products (dominant error = attn quantization 2^-11, measured-model
// calibrated to ~1.5e-4 rel on output).
// 2 CTAs/SM via __launch_bounds__(256,2); B-fragments processed in halves
// to stay under 128 regs.
// ============================================================================

#define LQn 2048
#define LKn 2048
#define Dn  768
#define Bn  8
#define MR  (Bn * LQn)          // 16384

typedef __half fp16;

// ---------------- static device scratch (no cudaMalloc allowed) -------------
static __device__ fp16 g_qin_h[(size_t)MR * Dn], g_qin_l[(size_t)MR * Dn];
static __device__ fp16 g_vin_h[(size_t)MR * Dn], g_vin_l[(size_t)MR * Dn];
static __device__ fp16 g_wq_h[(size_t)Dn * Dn],  g_wq_l[(size_t)Dn * Dn];
static __device__ fp16 g_wk_h[(size_t)Dn * Dn],  g_wk_l[(size_t)Dn * Dn];
static __device__ fp16 g_wv_h[(size_t)Dn * Dn],  g_wv_l[(size_t)Dn * Dn];
static __device__ fp16 g_q_h[(size_t)MR * Dn],   g_q_l[(size_t)MR * Dn];
static __device__ fp16 g_k_h[(size_t)MR * Dn],   g_k_l[(size_t)MR * Dn];
static __device__ fp16 g_v_h[(size_t)MR * Dn],   g_v_l[(size_t)MR * Dn];
static __device__ fp16 g_at[(size_t)Bn * LQn * LKn];     // single plane
static __device__ int  g_mask_mode;   // 0=byte, 1=int32, 2=float32

// ---------------- PTX helpers ------------------------------------------------
__device__ __forceinline__ uint32_t smem_u32(const void* p) {
    uint32_t a;
    asm("{ .reg .u64 t; cvta.to.shared.u64 t, %1; cvt.u32.u64 %0, t; }"
        : "=r"(a) : "l"(p));
    return a;
}

__device__ __forceinline__ void cpa16(uint32_t s, const void* g) {
    asm volatile("cp.async.cg.shared.global [%0], [%1], 16;"
                 :: "r"(s), "l"(g) : "memory");
}
#define CP_COMMIT() asm volatile("cp.async.commit_group;" ::: "memory")
#define CP_WAIT2()  asm volatile("cp.async.wait_group 2;"  ::: "memory")

__device__ __forceinline__ void ldsm4(uint32_t* r, uint32_t a) {
    asm volatile("ldmatrix.sync.aligned.m8n8.x4.shared.b16 {%0,%1,%2,%3}, [%4];"
                 : "=r"(r[0]), "=r"(r[1]), "=r"(r[2]), "=r"(r[3]) : "r"(a));
}
__device__ __forceinline__ void ldsm4t(uint32_t* r, uint32_t a) {
    asm volatile("ldmatrix.sync.aligned.m8n8.x4.trans.shared.b16 {%0,%1,%2,%3}, [%4];"
                 : "=r"(r[0]), "=r"(r[1]), "=r"(r[2]), "=r"(r[3]) : "r"(a));
}
__device__ __forceinline__ void mma16816(float* c, const uint32_t* a, const uint32_t* b) {
    asm volatile(
        "mma.sync.aligned.m16n8k16.row.col.f32.f16.f16.f32 "
        "{%0,%1,%2,%3}, {%4,%5,%6,%7}, {%8,%9}, {%0,%1,%2,%3};"
        : "+f"(c[0]), "+f"(c[1]), "+f"(c[2]), "+f"(c[3])
        : "r"(a[0]), "r"(a[1]), "r"(a[2]), "r"(a[3]), "r"(b[0]), "r"(b[1]));
}

__device__ __forceinline__ float sigf(float x) {
    return 1.0f / (1.0f + __expf(-x));
}

// ---------------- small kernels ----------------------------------------------
__global__ void detect_mask_kernel(const unsigned* __restrict__ w, int n) {
    int anyF = 0, anyO = 0;
    for (int i = threadIdx.x; i < n; i += blockDim.x) {
        unsigned x = w[i];
        anyF |= (x == 0x3F800000u);
        anyO |= (x != 0u && x != 1u && x != 0x3F800000u);
    }
    anyF = __syncthreads_or(anyF);
    anyO = __syncthreads_or(anyO);
    if (threadIdx.x == 0) g_mask_mode = anyF ? 2 : (anyO ? 0 : 1);
}

// split fp32 -> fp16 hi/lo planes (n4 = count/4)
__global__ void split_kernel(const float* __restrict__ s,
                             fp16* __restrict__ h, fp16* __restrict__ l, int n4) {
    int i = blockIdx.x * blockDim.x + threadIdx.x;
    if (i >= n4) return;
    float4 x = reinterpret_cast<const float4*>(s)[i];
    fp16 h0 = __float2half_rn(x.x), h1 = __float2half_rn(x.y);
    fp16 h2 = __float2half_rn(x.z), h3 = __float2half_rn(x.w);
    __half2 hh0 = __halves2half2(h0, h1);
    __half2 hh1 = __halves2half2(h2, h3);
    __half2 ll0 = __halves2half2(__float2half_rn(x.x - __half2float(h0)),
                                 __float2half_rn(x.y - __half2float(h1)));
    __half2 ll1 = __halves2half2(__float2half_rn(x.z - __half2float(h2)),
                                 __float2half_rn(x.w - __half2float(h3)));
    reinterpret_cast<__half2*>(h)[i * 2 + 0] = hh0;
    reinterpret_cast<__half2*>(h)[i * 2 + 1] = hh1;
    reinterpret_cast<__half2*>(l)[i * 2 + 0] = ll0;
    reinterpret_cast<__half2*>(l)[i * 2 + 1] = ll1;
}

// ---------------- GEMM --------------------------------------------------------
// CTA tile 128x128, BK=32, 8 warps (warp tile 32x64), 3-stage cp.async,
// 2 CTAs/SM.
// A: [M, lda] row-major plane(s). B:
//   BTRANS=false: [N, ldb] row-major (NT; ldmatrix non-trans)
//   BTRANS=true : [K, ldb] row-major (NN; ldmatrix trans)
// EPI: 0 = +bias, split-store fp16 hi/lo | 1 = mask+sigmoid, store fp16 single
//      | 2 = plain fp32 store.
// ASPLIT: A has hi+lo planes (3 products) vs single plane (2 products).
// Stage layout:
//   ASPLIT : Ah@0 Al@8K B h@16K B l@24K  (32 KB)
//   !ASPLIT: A @0       B h@8K  B l@16K  (24 KB)
// A-type tile: 128 rows x 32 k fp16, 64 B/row: addr = r*64 + (c ^ ((r>>1)&3))*16
// B NN tile:   32 k x 128 n fp16, 256 B/row:  addr = k*256 + (ns ^ (k&7))*16

template<int EPI, bool ASPLIT, bool BTRANS>
__global__ void __launch_bounds__(256, 2)
gemm_fp16(const fp16* __restrict__ Ah, const fp16* __restrict__ Al,
          const fp16* __restrict__ Bh, const fp16* __restrict__ Bl,
          fp16* __restrict__ Oh, fp16* __restrict__ Ol,
          float* __restrict__ Of,
          const float* __restrict__ bias, const void* __restrict__ mask,
          int lda, int ldb, int ldo, int K,
          long sA, long sB, long sO)
{
    extern __shared__ char smem[];
    const uint32_t sm0 = smem_u32(smem);

    constexpr uint32_t STAGE = ASPLIT ? 32768u : 24576u;
    constexpr uint32_t BOFF  = ASPLIT ? 16384u : 8192u;

    const int tid  = threadIdx.x;
    const int z    = blockIdx.z;
    const int mbase = blockIdx.y * 128;
    const int nbase = blockIdx.x * 128;

    Ah += (size_t)z * sA;  if (ASPLIT) Al += (size_t)z * sA;
    Bh += (size_t)z * sB;  Bl += (size_t)z * sB;

    const int warp = tid >> 5;
    const int lane = tid & 31;
    const int wm = warp >> 1;          // 0..3 -> rows wm*32
    const int wn = warp & 1;           // 0..1 -> cols wn*64
    const int m8 = lane >> 3;
    const int l8 = lane & 7;

    const int C = K >> 5;

    auto issue = [&](int c) {
        const int s = c - (c / 3) * 3;
        const uint32_t sb = sm0 + (uint32_t)s * STAGE;
        const size_t ka = (size_t)c * 32;
        // A plane(s)
        {
            const fp16* gh = Ah + (size_t)mbase * lda + ka;
            const fp16* gl = ASPLIT ? (Al + (size_t)mbase * lda + ka) : nullptr;
#pragma unroll
            for (int i = 0; i < 2; ++i) {
                int seg = tid + i * 256;          // 0..511
                int r = seg >> 2, cc = seg & 3;
                uint32_t sa = sb + r * 64 + ((cc ^ ((r >> 1) & 3)) << 4);
                cpa16(sa, gh + (size_t)r * lda + cc * 8);
                if (ASPLIT) cpa16(sa + 8192, gl + (size_t)r * lda + cc * 8);
            }
        }
        if (!BTRANS) {
            const fp16* gh = Bh + (size_t)nbase * ldb + ka;
            const fp16* gl = Bl + (size_t)nbase * ldb + ka;
#pragma unroll
            for (int i = 0; i < 2; ++i) {
                int seg = tid + i * 256;
                int r = seg >> 2, cc = seg & 3;
                uint32_t sa = sb + BOFF + r * 64 + ((cc ^ ((r >> 1) & 3)) << 4);
                cpa16(sa,        gh + (size_t)r * ldb + cc * 8);
                cpa16(sa + 8192, gl + (size_t)r * ldb + cc * 8);
            }
        } else {
            const fp16* gh = Bh + ka * ldb + nbase;
            const fp16* gl = Bl + ka * ldb + nbase;
#pragma unroll
            for (int i = 0; i < 2; ++i) {
                int seg = tid + i * 256;
                int k = seg >> 4, ns = seg & 15;
                uint32_t sa = sb + BOFF + k * 256 + ((ns ^ (k & 7)) << 4);
                cpa16(sa,        gh + (size_t)k * ldb + ns * 8);
                cpa16(sa + 8192, gl + (size_t)k * ldb + ns * 8);
            }
        }
    };

    issue(0); CP_COMMIT();
    issue(1); CP_COMMIT();
    issue(2); CP_COMMIT();

    float acc[2][8][4];
#pragma unroll
    for (int a = 0; a < 2; ++a)
#pragma unroll
        for (int b = 0; b < 8; ++b)
#pragma unroll
            for (int d = 0; d < 4; ++d) acc[a][b][d] = 0.0f;

    for (int c = 0; c < C; ++c) {
        CP_WAIT2();
        __syncthreads();

        const int s = c - (c / 3) * 3;
        const uint32_t sb = sm0 + (uint32_t)s * STAGE;

#pragma unroll
        for (int ks = 0; ks < 2; ++ks) {
            uint32_t ahf[2][4], alf[2][4];
#pragma unroll
            for (int mt = 0; mt < 2; ++mt) {
                int r = wm * 32 + mt * 16 + (m8 & 1) * 8 + l8;
                int cA = 2 * ks + (m8 >> 1);
                uint32_t off = r * 64 + ((cA ^ ((r >> 1) & 3)) << 4);
                ldsm4(ahf[mt], sb + off);
                if (ASPLIT) ldsm4(alf[mt], sb + 8192 + off);
            }
            // process n-tiles in two halves to bound register pressure
#pragma unroll
            for (int h2 = 0; h2 < 2; ++h2) {
                uint32_t bhf[2][4], blf[2][4];
#pragma unroll
                for (int gl = 0; gl < 2; ++gl) {
                    int g = h2 * 2 + gl;
                    if (!BTRANS) {
                        int n = wn * 64 + g * 16 + (m8 >> 1) * 8 + l8;
                        int cB = 2 * ks + (m8 & 1);
                        uint32_t off = n * 64 + ((cB ^ ((n >> 1) & 3)) << 4);
                        ldsm4(bhf[gl], sb + BOFF + off);
                        ldsm4(blf[gl], sb + BOFF + 8192 + off);
                    } else {
                        int k = ks * 16 + (m8 & 1) * 8 + l8;
                        int ns = ((wn * 64 + g * 16) >> 3) + (m8 >> 1);
                        uint32_t off = k * 256 + ((ns ^ (k & 7)) << 4);
                        ldsm4t(bhf[gl], sb + BOFF + off);
                        ldsm4t(blf[gl], sb + BOFF + 8192 + off);
                    }
                }
#pragma unroll
                for (int mt = 0; mt < 2; ++mt)
#pragma unroll
                    for (int ntl = 0; ntl < 4; ++ntl) {
                        const int nt = h2 * 4 + ntl;
                        const uint32_t* bH = &bhf[ntl >> 1][(ntl & 1) * 2];
                        const uint32_t* bL = &blf[ntl >> 1][(ntl & 1) * 2];
                        mma16816(acc[mt][nt], ahf[mt], bH);
                        mma16816(acc[mt][nt], ahf[mt], bL);
                        if (ASPLIT) mma16816(acc[mt][nt], alf[mt], bH);
                    }
            }
        }

        __syncthreads();
        if (c + 3 < C) issue(c + 3);
        CP_COMMIT();
    }

    // ---------------- epilogue ------------------------------------------------
    const int rb = mbase + wm * 32 + (lane >> 2);
    const int cb = nbase + wn * 64 + (lane & 3) * 2;
    const int mode = (EPI == 1) ? g_mask_mode : 0;

    if (EPI == 0) { Oh += (size_t)z * sO; Ol += (size_t)z * sO; }
    if (EPI == 1) { Oh += (size_t)z * sO; }
    if (EPI == 2) { Of += (size_t)z * sO; }

#pragma unroll
    for (int mt = 0; mt < 2; ++mt)
#pragma unroll
        for (int h = 0; h < 2; ++h) {
            const int gr = rb + mt * 16 + h * 8;
#pragma unroll
            for (int nt = 0; nt < 8; ++nt) {
                const int gc = cb + nt * 8;
                float x0 = acc[mt][nt][h * 2 + 0];
                float x1 = acc[mt][nt][h * 2 + 1];

                if (EPI == 0) {
                    x0 += bias[gc];
                    x1 += bias[gc + 1];
                } else if (EPI == 1) {
                    int f0, f1;
                    const size_t mo = (size_t)z * ((size_t)LQn * LKn)
                                    + (size_t)gr * LKn + gc;
                    if (mode == 0) {
                        const unsigned char* mp = (const unsigned char*)mask + mo;
                        f0 = mp[0]; f1 = mp[1];
                    } else if (mode == 1) {
                        const int* mp = (const int*)mask + mo;
                        f0 = mp[0]; f1 = mp[1];
                    } else {
                        const float* mp = (const float*)mask + mo;
                        f0 = (mp[0] != 0.0f); f1 = (mp[1] != 0.0f);
                    }
                    x0 = f0 ? sigf(x0) : 0.0f;
                    x1 = f1 ? sigf(x1) : 0.0f;
                }

                if (EPI == 2) {
                    float2 p; p.x = x0; p.y = x1;
                    *reinterpret_cast<float2*>(Of + (size_t)gr * ldo + gc) = p;
                } else if (EPI == 1) {
                    __half2 ph = __halves2half2(__float2half_rn(x0),
                                                __float2half_rn(x1));
                    *reinterpret_cast<__half2*>(Oh + (size_t)gr * ldo + gc) = ph;
                } else {
                    fp16 h0 = __float2half_rn(x0), h1 = __float2half_rn(x1);
                    __half2 ph = __halves2half2(h0, h1);
                    __half2 pl = __halves2half2(
                        __float2half_rn(x0 - __half2float(h0)),
                        __float2half_rn(x1 - __half2float(h1)));
                    *reinterpret_cast<__half2*>(Oh + (size_t)gr * ldo + gc) = ph;
                    *reinterpret_cast<__half2*>(Ol + (size_t)gr * ldo + gc) = pl;
                }
            }
        }
}

// ---------------- host side ---------------------------------------------------
extern "C" void kernel_launch(void* const* d_in, const int* in_sizes, int n_in,
                              void* d_out, int out_size)
{
    const float* queries = (const float*)d_in[0];
    const float* values  = (const float*)d_in[1];
    const void*  mask    = d_in[2];
    const float* Wq = (const float*)d_in[3];
    const float* bq = (const float*)d_in[4];
    const float* Wk = (const float*)d_in[5];
    const float* bk = (const float*)d_in[6];
    const float* Wv = (const float*)d_in[7];
    const float* bv = (const float*)d_in[8];
    float* out = (float*)d_out;

    fp16 *qin_h, *qin_l, *vin_h, *vin_l;
    fp16 *wq_h, *wq_l, *wk_h, *wk_l, *wv_h, *wv_l;
    fp16 *q_h, *q_l, *k_h, *k_l, *v_h, *v_l, *at;
    cudaGetSymbolAddress((void**)&qin_h, g_qin_h);
    cudaGetSymbolAddress((void**)&qin_l, g_qin_l);
    cudaGetSymbolAddress((void**)&vin_h, g_vin_h);
    cudaGetSymbolAddress((void**)&vin_l, g_vin_l);
    cudaGetSymbolAddress((void**)&wq_h, g_wq_h);
    cudaGetSymbolAddress((void**)&wq_l, g_wq_l);
    cudaGetSymbolAddress((void**)&wk_h, g_wk_h);
    cudaGetSymbolAddress((void**)&wk_l, g_wk_l);
    cudaGetSymbolAddress((void**)&wv_h, g_wv_h);
    cudaGetSymbolAddress((void**)&wv_l, g_wv_l);
    cudaGetSymbolAddress((void**)&q_h, g_q_h);
    cudaGetSymbolAddress((void**)&q_l, g_q_l);
    cudaGetSymbolAddress((void**)&k_h, g_k_h);
    cudaGetSymbolAddress((void**)&k_l, g_k_l);
    cudaGetSymbolAddress((void**)&v_h, g_v_h);
    cudaGetSymbolAddress((void**)&v_l, g_v_l);
    cudaGetSymbolAddress((void**)&at, g_at);

    constexpr int SMEM_S = 3 * 32768;   // 96 KB (ASPLIT kernels)
    constexpr int SMEM_C = 3 * 24576;   // 72 KB (context)
    static int attr_done = 0;
    if (!attr_done) {
        cudaFuncSetAttribute(gemm_fp16<0, true, false>,
                             cudaFuncAttributeMaxDynamicSharedMemorySize, SMEM_S);
        cudaFuncSetAttribute(gemm_fp16<1, true, false>,
                             cudaFuncAttributeMaxDynamicSharedMemorySize, SMEM_S);
        cudaFuncSetAttribute(gemm_fp16<2, false, true>,
                             cudaFuncAttributeMaxDynamicSharedMemorySize, SMEM_C);
        attr_done = 1;
    }

    detect_mask_kernel<<<1, 256>>>((const unsigned*)mask, 8192);

    {
        int n4 = MR * Dn / 4;
        split_kernel<<<(n4 + 255) / 256, 256>>>(queries, qin_h, qin_l, n4);
        split_kernel<<<(n4 + 255) / 256, 256>>>(values,  vin_h, vin_l, n4);
        int w4 = Dn * Dn / 4;
        split_kernel<<<(w4 + 255) / 256, 256>>>(Wq, wq_h, wq_l, w4);
        split_kernel<<<(w4 + 255) / 256, 256>>>(Wk, wk_h, wk_l, w4);
        split_kernel<<<(w4 + 255) / 256, 256>>>(Wv, wv_h, wv_l, w4);
    }

    // q = queries @ Wq^T + bq
    gemm_fp16<0, true, false><<<dim3(6, 128, 1), 256, SMEM_S>>>(
        qin_h, qin_l, wq_h, wq_l, q_h, q_l, nullptr, bq, nullptr,
        Dn, Dn, Dn, Dn, 0, 0, 0);
    // v = values @ Wv^T + bv
    gemm_fp16<0, true, false><<<dim3(6, 128, 1), 256, SMEM_S>>>(
        vin_h, vin_l, wv_h, wv_l, v_h, v_l, nullptr, bv, nullptr,
        Dn, Dn, Dn, Dn, 0, 0, 0);
    // k = v @ Wk^T + bk
    gemm_fp16<0, true, false><<<dim3(6, 128, 1), 256, SMEM_S>>>(
        v_h, v_l, wk_h, wk_l, k_h, k_l, nullptr, bk, nullptr,
        Dn, Dn, Dn, Dn, 0, 0, 0);
    // attn = sigmoid(mask ? q@k^T : -1e9) -> single fp16 plane, per batch
    gemm_fp16<1, true, false><<<dim3(16, 16, Bn), 256, SMEM_S>>>(
        q_h, q_l, k_h, k_l, at, nullptr, nullptr, nullptr, mask,
        Dn, Dn, LKn, Dn,
        (long)LQn * Dn, (long)LKn * Dn, (long)LQn * LKn);
    // out = attn @ v (NN), 2 products, per batch
    gemm_fp16<2, false, true><<<dim3(6, 16, Bn), 256, SMEM_C>>>(
        at, nullptr, v_h, v_l, nullptr, nullptr, out, nullptr, nullptr,
        LKn, Dn, Dn, LKn,
        (long)LQn * LKn, (long)LKn * Dn, (long)LQn * Dn);
}

// round 6
// speedup vs baseline: 1.8016x; 1.2744x over previous
#include <cuda_runtime.h>
#include <cuda_fp16.h>
#include <cstdint>
#include <cstddef>

// ============================================================================
// Problem: B=8, Lq=Lk=2048, D=768
//   q = queries@Wq^T+bq ; v = values@Wv^T+bv ; k = v@Wk^T+bk
//   attn = sigmoid(mask ? q@k^T : -1e9) ; out = attn@v
//
// Plain sm_100 target (no tcgen05). Base-ISA tensor path:
// mma.sync.m16n8k16.f32.f16.f16.f32 + ldmatrix + cp.async.
//
// Precision scheme (calibrated against measured rel_err):
//   Every GEMM computes 2 products: A_hi*(B_hi + B_lo). A is single fp16
//   plane everywhere; only B operands (weights, k, v) keep hi/lo pairs.
//   Measured-calibrated predicted output rel_err ~3e-4 (threshold 1e-3).
// Pipeline: 128x128 CTA tile, BK=32, 8 warps, 4-stage cp.async (24 KB/stage),
// 2 CTAs/SM.
// (Round-5 resubmit: previous bench attempt hit an infra failure, kernel
//  never ran.)
// ============================================================================

#define LQn 2048
#define LKn 2048
#define Dn  768
#define Bn  8
#define MR  (Bn * LQn)          // 16384

typedef __half fp16;

// ---------------- static device scratch (no cudaMalloc allowed) -------------
static __device__ fp16 g_qin[(size_t)MR * Dn];
static __device__ fp16 g_vin[(size_t)MR * Dn];
static __device__ fp16 g_wq_h[(size_t)Dn * Dn],  g_wq_l[(size_t)Dn * Dn];
static __device__ fp16 g_wk_h[(size_t)Dn * Dn],  g_wk_l[(size_t)Dn * Dn];
static __device__ fp16 g_wv_h[(size_t)Dn * Dn],  g_wv_l[(size_t)Dn * Dn];
static __device__ fp16 g_q[(size_t)MR * Dn];                       // hi only
static __device__ fp16 g_k_h[(size_t)MR * Dn],   g_k_l[(size_t)MR * Dn];
static __device__ fp16 g_v_h[(size_t)MR * Dn],   g_v_l[(size_t)MR * Dn];
static __device__ fp16 g_at[(size_t)Bn * LQn * LKn];               // single plane
static __device__ int  g_mask_mode;   // 0=byte, 1=int32, 2=float32

// ---------------- PTX helpers ------------------------------------------------
__device__ __forceinline__ uint32_t smem_u32(const void* p) {
    uint32_t a;
    asm("{ .reg .u64 t; cvta.to.shared.u64 t, %1; cvt.u32.u64 %0, t; }"
        : "=r"(a) : "l"(p));
    return a;
}

__device__ __forceinline__ void cpa16(uint32_t s, const void* g) {
    asm volatile("cp.async.cg.shared.global [%0], [%1], 16;"
                 :: "r"(s), "l"(g) : "memory");
}
#define CP_COMMIT() asm volatile("cp.async.commit_group;" ::: "memory")
#define CP_WAIT3()  asm volatile("cp.async.wait_group 3;"  ::: "memory")

__device__ __forceinline__ void ldsm4(uint32_t* r, uint32_t a) {
    asm volatile("ldmatrix.sync.aligned.m8n8.x4.shared.b16 {%0,%1,%2,%3}, [%4];"
                 : "=r"(r[0]), "=r"(r[1]), "=r"(r[2]), "=r"(r[3]) : "r"(a));
}
__device__ __forceinline__ void ldsm4t(uint32_t* r, uint32_t a) {
    asm volatile("ldmatrix.sync.aligned.m8n8.x4.trans.shared.b16 {%0,%1,%2,%3}, [%4];"
                 : "=r"(r[0]), "=r"(r[1]), "=r"(r[2]), "=r"(r[3]) : "r"(a));
}
__device__ __forceinline__ void mma16816(float* c, const uint32_t* a, const uint32_t* b) {
    asm volatile(
        "mma.sync.aligned.m16n8k16.row.col.f32.f16.f16.f32 "
        "{%0,%1,%2,%3}, {%4,%5,%6,%7}, {%8,%9}, {%0,%1,%2,%3};"
        : "+f"(c[0]), "+f"(c[1]), "+f"(c[2]), "+f"(c[3])
        : "r"(a[0]), "r"(a[1]), "r"(a[2]), "r"(a[3]), "r"(b[0]), "r"(b[1]));
}

__device__ __forceinline__ float sigf(float x) {
    return 1.0f / (1.0f + __expf(-x));
}

// ---------------- small kernels ----------------------------------------------
__global__ void detect_mask_kernel(const unsigned* __restrict__ w, int n) {
    int anyF = 0, anyO = 0;
    for (int i = threadIdx.x; i < n; i += blockDim.x) {
        unsigned x = w[i];
        anyF |= (x == 0x3F800000u);
        anyO |= (x != 0u && x != 1u && x != 0x3F800000u);
    }
    anyF = __syncthreads_or(anyF);
    anyO = __syncthreads_or(anyO);
    if (threadIdx.x == 0) g_mask_mode = anyF ? 2 : (anyO ? 0 : 1);
}

// plain fp32 -> fp16 convert (n4 = count/4)
__global__ void conv_kernel(const float* __restrict__ s,
                            fp16* __restrict__ h, int n4) {
    int i = blockIdx.x * blockDim.x + threadIdx.x;
    if (i >= n4) return;
    float4 x = reinterpret_cast<const float4*>(s)[i];
    __half2 h0 = __halves2half2(__float2half_rn(x.x), __float2half_rn(x.y));
    __half2 h1 = __halves2half2(__float2half_rn(x.z), __float2half_rn(x.w));
    reinterpret_cast<__half2*>(h)[i * 2 + 0] = h0;
    reinterpret_cast<__half2*>(h)[i * 2 + 1] = h1;
}

// split fp32 -> fp16 hi/lo planes (n4 = count/4)
__global__ void split_kernel(const float* __restrict__ s,
                             fp16* __restrict__ h, fp16* __restrict__ l, int n4) {
    int i = blockIdx.x * blockDim.x + threadIdx.x;
    if (i >= n4) return;
    float4 x = reinterpret_cast<const float4*>(s)[i];
    fp16 h0 = __float2half_rn(x.x), h1 = __float2half_rn(x.y);
    fp16 h2 = __float2half_rn(x.z), h3 = __float2half_rn(x.w);
    __half2 hh0 = __halves2half2(h0, h1);
    __half2 hh1 = __halves2half2(h2, h3);
    __half2 ll0 = __halves2half2(__float2half_rn(x.x - __half2float(h0)),
                                 __float2half_rn(x.y - __half2float(h1)));
    __half2 ll1 = __halves2half2(__float2half_rn(x.z - __half2float(h2)),
                                 __float2half_rn(x.w - __half2float(h3)));
    reinterpret_cast<__half2*>(h)[i * 2 + 0] = hh0;
    reinterpret_cast<__half2*>(h)[i * 2 + 1] = hh1;
    reinterpret_cast<__half2*>(l)[i * 2 + 0] = ll0;
    reinterpret_cast<__half2*>(l)[i * 2 + 1] = ll1;
}

// ---------------- GEMM --------------------------------------------------------
// CTA tile 128x128, BK=32, 8 warps (warp tile 32x64), 4-stage cp.async,
// 2 CTAs/SM. A single plane; B hi/lo pair; acc += A*(Bh + Bl).
// A: [M, lda] row-major. B:
//   BTRANS=false: [N, ldb] row-major (NT; ldmatrix non-trans)
//   BTRANS=true : [K, ldb] row-major (NN; ldmatrix trans)
// EPI: 0 = +bias, store fp16 hi/lo | 1 = mask+sigmoid, store fp16 single
//      | 2 = plain fp32 store | 3 = +bias, store fp16 single.
// Stage layout (24 KB): A@0  Bh@8K  Bl@16K
// A-type tile: 128 rows x 32 k fp16, 64 B/row: addr = r*64 + (c ^ ((r>>1)&3))*16
// B NN tile:   32 k x 128 n fp16, 256 B/row:  addr = k*256 + (ns ^ (k&7))*16

template<int EPI, bool BTRANS>
__global__ void __launch_bounds__(256, 2)
gemm_fp16(const fp16* __restrict__ Ap, const fp16* __restrict__ Bh,
          const fp16* __restrict__ Bl,
          fp16* __restrict__ Oh, fp16* __restrict__ Ol,
          float* __restrict__ Of,
          const float* __restrict__ bias, const void* __restrict__ mask,
          int lda, int ldb, int ldo, int K,
          long sA, long sB, long sO)
{
    extern __shared__ char smem[];
    const uint32_t sm0 = smem_u32(smem);

    constexpr uint32_t STAGE = 24576u;

    const int tid  = threadIdx.x;
    const int z    = blockIdx.z;
    const int mbase = blockIdx.y * 128;
    const int nbase = blockIdx.x * 128;

    Ap += (size_t)z * sA;
    Bh += (size_t)z * sB;  Bl += (size_t)z * sB;

    const int warp = tid >> 5;
    const int lane = tid & 31;
    const int wm = warp >> 1;          // 0..3 -> rows wm*32
    const int wn = warp & 1;           // 0..1 -> cols wn*64
    const int m8 = lane >> 3;
    const int l8 = lane & 7;

    const int C = K >> 5;

    auto issue = [&](int c) {
        const int s = c & 3;
        const uint32_t sb = sm0 + (uint32_t)s * STAGE;
        const size_t ka = (size_t)c * 32;
        // A (single plane): 512 x 16B segments; 256 threads x 2
        {
            const fp16* ga = Ap + (size_t)mbase * lda + ka;
#pragma unroll
            for (int i = 0; i < 2; ++i) {
                int seg = tid + i * 256;          // 0..511
                int r = seg >> 2, cc = seg & 3;
                uint32_t sa = sb + r * 64 + ((cc ^ ((r >> 1) & 3)) << 4);
                cpa16(sa, ga + (size_t)r * lda + cc * 8);
            }
        }
        if (!BTRANS) {
            const fp16* gh = Bh + (size_t)nbase * ldb + ka;
            const fp16* gl = Bl + (size_t)nbase * ldb + ka;
#pragma unroll
            for (int i = 0; i < 2; ++i) {
                int seg = tid + i * 256;
                int r = seg >> 2, cc = seg & 3;
                uint32_t sa = sb + 8192 + r * 64 + ((cc ^ ((r >> 1) & 3)) << 4);
                cpa16(sa,        gh + (size_t)r * ldb + cc * 8);
                cpa16(sa + 8192, gl + (size_t)r * ldb + cc * 8);
            }
        } else {
            const fp16* gh = Bh + ka * ldb + nbase;
            const fp16* gl = Bl + ka * ldb + nbase;
#pragma unroll
            for (int i = 0; i < 2; ++i) {
                int seg = tid + i * 256;
                int k = seg >> 4, ns = seg & 15;
                uint32_t sa = sb + 8192 + k * 256 + ((ns ^ (k & 7)) << 4);
                cpa16(sa,        gh + (size_t)k * ldb + ns * 8);
                cpa16(sa + 8192, gl + (size_t)k * ldb + ns * 8);
            }
        }
    };

    issue(0); CP_COMMIT();
    issue(1); CP_COMMIT();
    issue(2); CP_COMMIT();
    issue(3); CP_COMMIT();

    float acc[2][8][4];
#pragma unroll
    for (int a = 0; a < 2; ++a)
#pragma unroll
        for (int b = 0; b < 8; ++b)
#pragma unroll
            for (int d = 0; d < 4; ++d) acc[a][b][d] = 0.0f;

    for (int c = 0; c < C; ++c) {
        CP_WAIT3();
        __syncthreads();

        const uint32_t sb = sm0 + (uint32_t)(c & 3) * STAGE;

#pragma unroll
        for (int ks = 0; ks < 2; ++ks) {
            uint32_t ahf[2][4];
#pragma unroll
            for (int mt = 0; mt < 2; ++mt) {
                int r = wm * 32 + mt * 16 + (m8 & 1) * 8 + l8;
                int cA = 2 * ks + (m8 >> 1);
                uint32_t off = r * 64 + ((cA ^ ((r >> 1) & 3)) << 4);
                ldsm4(ahf[mt], sb + off);
            }
            // process n-tiles in two halves to bound register pressure
#pragma unroll
            for (int h2 = 0; h2 < 2; ++h2) {
                uint32_t bhf[2][4], blf[2][4];
#pragma unroll
                for (int gl = 0; gl < 2; ++gl) {
                    int g = h2 * 2 + gl;
                    if (!BTRANS) {
                        int n = wn * 64 + g * 16 + (m8 >> 1) * 8 + l8;
                        int cB = 2 * ks + (m8 & 1);
                        uint32_t off = n * 64 + ((cB ^ ((n >> 1) & 3)) << 4);
                        ldsm4(bhf[gl], sb + 8192 + off);
                        ldsm4(blf[gl], sb + 16384 + off);
                    } else {
                        int k = ks * 16 + (m8 & 1) * 8 + l8;
                        int ns = ((wn * 64 + g * 16) >> 3) + (m8 >> 1);
                        uint32_t off = k * 256 + ((ns ^ (k & 7)) << 4);
                        ldsm4t(bhf[gl], sb + 8192 + off);
                        ldsm4t(blf[gl], sb + 16384 + off);
                    }
                }
#pragma unroll
                for (int mt = 0; mt < 2; ++mt)
#pragma unroll
                    for (int ntl = 0; ntl < 4; ++ntl) {
                        const int nt = h2 * 4 + ntl;
                        const uint32_t* bH = &bhf[ntl >> 1][(ntl & 1) * 2];
                        const uint32_t* bL = &blf[ntl >> 1][(ntl & 1) * 2];
                        mma16816(acc[mt][nt], ahf[mt], bH);
                        mma16816(acc[mt][nt], ahf[mt], bL);
                    }
            }
        }

        __syncthreads();
        if (c + 4 < C) issue(c + 4);
        CP_COMMIT();
    }

    // ---------------- epilogue ------------------------------------------------
    const int rb = mbase + wm * 32 + (lane >> 2);
    const int cb = nbase + wn * 64 + (lane & 3) * 2;
    const int mode = (EPI == 1) ? g_mask_mode : 0;

    if (EPI == 0) { Oh += (size_t)z * sO; Ol += (size_t)z * sO; }
    if (EPI == 1 || EPI == 3) { Oh += (size_t)z * sO; }
    if (EPI == 2) { Of += (size_t)z * sO; }

#pragma unroll
    for (int mt = 0; mt < 2; ++mt)
#pragma unroll
        for (int h = 0; h < 2; ++h) {
            const int gr = rb + mt * 16 + h * 8;
#pragma unroll
            for (int nt = 0; nt < 8; ++nt) {
                const int gc = cb + nt * 8;
                float x0 = acc[mt][nt][h * 2 + 0];
                float x1 = acc[mt][nt][h * 2 + 1];

                if (EPI == 0 || EPI == 3) {
                    x0 += bias[gc];
                    x1 += bias[gc + 1];
                } else if (EPI == 1) {
                    int f0, f1;
                    const size_t mo = (size_t)z * ((size_t)LQn * LKn)
                                    + (size_t)gr * LKn + gc;
                    if (mode == 0) {
                        const unsigned char* mp = (const unsigned char*)mask + mo;
                        f0 = mp[0]; f1 = mp[1];
                    } else if (mode == 1) {
                        const int* mp = (const int*)mask + mo;
                        f0 = mp[0]; f1 = mp[1];
                    } else {
                        const float* mp = (const float*)mask + mo;
                        f0 = (mp[0] != 0.0f); f1 = (mp[1] != 0.0f);
                    }
                    x0 = f0 ? sigf(x0) : 0.0f;
                    x1 = f1 ? sigf(x1) : 0.0f;
                }

                if (EPI == 2) {
                    float2 p; p.x = x0; p.y = x1;
                    *reinterpret_cast<float2*>(Of + (size_t)gr * ldo + gc) = p;
                } else if (EPI == 1 || EPI == 3) {
                    __half2 ph = __halves2half2(__float2half_rn(x0),
                                                __float2half_rn(x1));
                    *reinterpret_cast<__half2*>(Oh + (size_t)gr * ldo + gc) = ph;
                } else {
                    fp16 h0 = __float2half_rn(x0), h1 = __float2half_rn(x1);
                    __half2 ph = __halves2half2(h0, h1);
                    __half2 pl = __halves2half2(
                        __float2half_rn(x0 - __half2float(h0)),
                        __float2half_rn(x1 - __half2float(h1)));
                    *reinterpret_cast<__half2*>(Oh + (size_t)gr * ldo + gc) = ph;
                    *reinterpret_cast<__half2*>(Ol + (size_t)gr * ldo + gc) = pl;
                }
            }
        }
}

// ---------------- host side ---------------------------------------------------
extern "C" void kernel_launch(void* const* d_in, const int* in_sizes, int n_in,
                              void* d_out, int out_size)
{
    const float* queries = (const float*)d_in[0];
    const float* values  = (const float*)d_in[1];
    const void*  mask    = d_in[2];
    const float* Wq = (const float*)d_in[3];
    const float* bq = (const float*)d_in[4];
    const float* Wk = (const float*)d_in[5];
    const float* bk = (const float*)d_in[6];
    const float* Wv = (const float*)d_in[7];
    const float* bv = (const float*)d_in[8];
    float* out = (float*)d_out;

    fp16 *qin, *vin;
    fp16 *wq_h, *wq_l, *wk_h, *wk_l, *wv_h, *wv_l;
    fp16 *q, *k_h, *k_l, *v_h, *v_l, *at;
    cudaGetSymbolAddress((void**)&qin, g_qin);
    cudaGetSymbolAddress((void**)&vin, g_vin);
    cudaGetSymbolAddress((void**)&wq_h, g_wq_h);
    cudaGetSymbolAddress((void**)&wq_l, g_wq_l);
    cudaGetSymbolAddress((void**)&wk_h, g_wk_h);
    cudaGetSymbolAddress((void**)&wk_l, g_wk_l);
    cudaGetSymbolAddress((void**)&wv_h, g_wv_h);
    cudaGetSymbolAddress((void**)&wv_l, g_wv_l);
    cudaGetSymbolAddress((void**)&q,   g_q);
    cudaGetSymbolAddress((void**)&k_h, g_k_h);
    cudaGetSymbolAddress((void**)&k_l, g_k_l);
    cudaGetSymbolAddress((void**)&v_h, g_v_h);
    cudaGetSymbolAddress((void**)&v_l, g_v_l);
    cudaGetSymbolAddress((void**)&at,  g_at);

    constexpr int SMEM = 4 * 24576;   // 96 KB
    static int attr_done = 0;
    if (!attr_done) {
        cudaFuncSetAttribute(gemm_fp16<0, false>,
                             cudaFuncAttributeMaxDynamicSharedMemorySize, SMEM);
        cudaFuncSetAttribute(gemm_fp16<3, false>,
                             cudaFuncAttributeMaxDynamicSharedMemorySize, SMEM);
        cudaFuncSetAttribute(gemm_fp16<1, false>,
                             cudaFuncAttributeMaxDynamicSharedMemorySize, SMEM);
        cudaFuncSetAttribute(gemm_fp16<2, true>,
                             cudaFuncAttributeMaxDynamicSharedMemorySize, SMEM);
        attr_done = 1;
    }

    detect_mask_kernel<<<1, 256>>>((const unsigned*)mask, 8192);

    {
        int n4 = MR * Dn / 4;
        conv_kernel<<<(n4 + 255) / 256, 256>>>(queries, qin, n4);
        conv_kernel<<<(n4 + 255) / 256, 256>>>(values,  vin, n4);
        int w4 = Dn * Dn / 4;
        split_kernel<<<(w4 + 255) / 256, 256>>>(Wq, wq_h, wq_l, w4);
        split_kernel<<<(w4 + 255) / 256, 256>>>(Wk, wk_h, wk_l, w4);
        split_kernel<<<(w4 + 255) / 256, 256>>>(Wv, wv_h, wv_l, w4);
    }

    // q = queries @ Wq^T + bq -> single plane
    gemm_fp16<3, false><<<dim3(6, 128, 1), 256, SMEM>>>(
        qin, wq_h, wq_l, q, nullptr, nullptr, bq, nullptr,
        Dn, Dn, Dn, Dn, 0, 0, 0);
    // v = values @ Wv^T + bv -> hi/lo (B of context)
    gemm_fp16<0, false><<<dim3(6, 128, 1), 256, SMEM>>>(
        vin, wv_h, wv_l, v_h, v_l, nullptr, bv, nullptr,
        Dn, Dn, Dn, Dn, 0, 0, 0);
    // k = v_hi @ Wk^T + bk -> hi/lo (B of score)
    gemm_fp16<0, false><<<dim3(6, 128, 1), 256, SMEM>>>(
        v_h, wk_h, wk_l, k_h, k_l, nullptr, bk, nullptr,
        Dn, Dn, Dn, Dn, 0, 0, 0);
    // attn = sigmoid(mask ? q@k^T : -1e9) -> single fp16 plane, per batch
    gemm_fp16<1, false><<<dim3(16, 16, Bn), 256, SMEM>>>(
        q, k_h, k_l, at, nullptr, nullptr, nullptr, mask,
        Dn, Dn, LKn, Dn,
        (long)LQn * Dn, (long)LKn * Dn, (long)LQn * LKn);
    // out = attn @ v (NN), per batch
    gemm_fp16<2, true><<<dim3(6, 16, Bn), 256, SMEM>>>(
        at, v_h, v_l, nullptr, nullptr, out, nullptr, nullptr,
        LKn, Dn, Dn, LKn,
        (long)LQn * LKn, (long)LKn * Dn, (long)LQn * Dn);
}

// round 8
// speedup vs baseline: 1.8409x; 1.0219x over previous
#include <cuda_runtime.h>
#include <cuda_fp16.h>
#include <cstdint>
#include <cstddef>

// ============================================================================
// Problem: B=8, Lq=Lk=2048, D=768
//   q = queries@Wq^T+bq ; v = values@Wv^T+bv ; k = v@Wk^T+bk
//   attn = sigmoid(mask ? q@k^T : -1e9) ; out = attn@v
//
// Plain sm_100 target. mma.sync.m16n8k16.f32.f16.f16.f32 + ldmatrix + cp.async.
// Precision: A single fp16 plane, B hi/lo pair, acc += A*Bh + A*Bl.
// R7 changes vs R6 (1032us):
//  - inner loop emits all bH mmas then all bL mmas (kills dependent
//    back-to-back mma on the same accumulator)
//  - single __syncthreads per K-chunk (issue c+3 right after sync; with 4
//    stages + 3 groups in flight it targets the stage drained last iter)
//  - prep fused into one kernel (score GEMM = launch #6 for ncu -s 5)
// (Resubmit: previous bench attempt hit an infra failure, kernel never ran.)
// ============================================================================

#define LQn 2048
#define LKn 2048
#define Dn  768
#define Bn  8
#define MR  (Bn * LQn)          // 16384

typedef __half fp16;

// ---------------- static device scratch (no cudaMalloc allowed) -------------
static __device__ fp16 g_qin[(size_t)MR * Dn];
static __device__ fp16 g_vin[(size_t)MR * Dn];
static __device__ fp16 g_wq_h[(size_t)Dn * Dn],  g_wq_l[(size_t)Dn * Dn];
static __device__ fp16 g_wk_h[(size_t)Dn * Dn],  g_wk_l[(size_t)Dn * Dn];
static __device__ fp16 g_wv_h[(size_t)Dn * Dn],  g_wv_l[(size_t)Dn * Dn];
static __device__ fp16 g_q[(size_t)MR * Dn];                       // hi only
static __device__ fp16 g_k_h[(size_t)MR * Dn],   g_k_l[(size_t)MR * Dn];
static __device__ fp16 g_v_h[(size_t)MR * Dn],   g_v_l[(size_t)MR * Dn];
static __device__ fp16 g_at[(size_t)Bn * LQn * LKn];               // single plane
static __device__ int  g_mask_mode;   // 0=byte, 1=int32, 2=float32

// ---------------- PTX helpers ------------------------------------------------
__device__ __forceinline__ uint32_t smem_u32(const void* p) {
    uint32_t a;
    asm("{ .reg .u64 t; cvta.to.shared.u64 t, %1; cvt.u32.u64 %0, t; }"
        : "=r"(a) : "l"(p));
    return a;
}

__device__ __forceinline__ void cpa16(uint32_t s, const void* g) {
    asm volatile("cp.async.cg.shared.global [%0], [%1], 16;"
                 :: "r"(s), "l"(g) : "memory");
}
#define CP_COMMIT() asm volatile("cp.async.commit_group;" ::: "memory")
#define CP_WAIT2()  asm volatile("cp.async.wait_group 2;"  ::: "memory")

__device__ __forceinline__ void ldsm4(uint32_t* r, uint32_t a) {
    asm volatile("ldmatrix.sync.aligned.m8n8.x4.shared.b16 {%0,%1,%2,%3}, [%4];"
                 : "=r"(r[0]), "=r"(r[1]), "=r"(r[2]), "=r"(r[3]) : "r"(a));
}
__device__ __forceinline__ void ldsm4t(uint32_t* r, uint32_t a) {
    asm volatile("ldmatrix.sync.aligned.m8n8.x4.trans.shared.b16 {%0,%1,%2,%3}, [%4];"
                 : "=r"(r[0]), "=r"(r[1]), "=r"(r[2]), "=r"(r[3]) : "r"(a));
}
__device__ __forceinline__ void mma16816(float* c, const uint32_t* a, const uint32_t* b) {
    asm volatile(
        "mma.sync.aligned.m16n8k16.row.col.f32.f16.f16.f32 "
        "{%0,%1,%2,%3}, {%4,%5,%6,%7}, {%8,%9}, {%0,%1,%2,%3};"
        : "+f"(c[0]), "+f"(c[1]), "+f"(c[2]), "+f"(c[3])
        : "r"(a[0]), "r"(a[1]), "r"(a[2]), "r"(a[3]), "r"(b[0]), "r"(b[1]));
}

__device__ __forceinline__ float sigf(float x) {
    return 1.0f / (1.0f + __expf(-x));
}

// ---------------- small kernels ----------------------------------------------
__global__ void detect_mask_kernel(const unsigned* __restrict__ w, int n) {
    int anyF = 0, anyO = 0;
    for (int i = threadIdx.x; i < n; i += blockDim.x) {
        unsigned x = w[i];
        anyF |= (x == 0x3F800000u);
        anyO |= (x != 0u && x != 1u && x != 0x3F800000u);
    }
    anyF = __syncthreads_or(anyF);
    anyO = __syncthreads_or(anyO);
    if (threadIdx.x == 0) g_mask_mode = anyF ? 2 : (anyO ? 0 : 1);
}

// Fused prep: convert queries/values -> fp16 plane; split Wq/Wk/Wv -> hi/lo.
// One float4 per thread across five concatenated ranges.
__global__ void prep_kernel(const float* __restrict__ queries,
                            const float* __restrict__ values,
                            const float* __restrict__ Wq,
                            const float* __restrict__ Wk,
                            const float* __restrict__ Wv) {
    const int N4 = MR * Dn / 4;          // 3,145,728
    const int W4 = Dn * Dn / 4;          // 147,456
    int i = blockIdx.x * blockDim.x + threadIdx.x;

    const float* src;
    fp16 *dh, *dl = nullptr;
    int j = i;
    if (j < N4)                 { src = queries; dh = g_qin; }
    else if ((j -= N4) < N4)    { src = values;  dh = g_vin; }
    else if ((j -= N4) < W4)    { src = Wq; dh = g_wq_h; dl = g_wq_l; }
    else if ((j -= W4) < W4)    { src = Wk; dh = g_wk_h; dl = g_wk_l; }
    else if ((j -= W4) < W4)    { src = Wv; dh = g_wv_h; dl = g_wv_l; }
    else return;

    float4 x = reinterpret_cast<const float4*>(src)[j];
    fp16 h0 = __float2half_rn(x.x), h1 = __float2half_rn(x.y);
    fp16 h2 = __float2half_rn(x.z), h3 = __float2half_rn(x.w);
    reinterpret_cast<__half2*>(dh)[j * 2 + 0] = __halves2half2(h0, h1);
    reinterpret_cast<__half2*>(dh)[j * 2 + 1] = __halves2half2(h2, h3);
    if (dl) {
        __half2 l0 = __halves2half2(__float2half_rn(x.x - __half2float(h0)),
                                    __float2half_rn(x.y - __half2float(h1)));
        __half2 l1 = __halves2half2(__float2half_rn(x.z - __half2float(h2)),
                                    __float2half_rn(x.w - __half2float(h3)));
        reinterpret_cast<__half2*>(dl)[j * 2 + 0] = l0;
        reinterpret_cast<__half2*>(dl)[j * 2 + 1] = l1;
    }
}

// ---------------- GEMM --------------------------------------------------------
// CTA tile 128x128, BK=32, 8 warps (warp tile 32x64), 4 stage buffers with
// 3 cp.async groups in flight, ONE __syncthreads per chunk, 2 CTAs/SM.
// A single plane; B hi/lo pair; acc += A*Bh + A*Bl (bH batch then bL batch).
// EPI: 0 = +bias, store fp16 hi/lo | 1 = mask+sigmoid, store fp16 single
//      | 2 = plain fp32 store | 3 = +bias, store fp16 single.
// Stage layout (24 KB): A@0  Bh@8K  Bl@16K
// A-type tile: 128 rows x 32 k fp16, 64 B/row: addr = r*64 + (c ^ ((r>>1)&3))*16
// B NN tile:   32 k x 128 n fp16, 256 B/row:  addr = k*256 + (ns ^ (k&7))*16

template<int EPI, bool BTRANS>
__global__ void __launch_bounds__(256, 2)
gemm_fp16(const fp16* __restrict__ Ap, const fp16* __restrict__ Bh,
          const fp16* __restrict__ Bl,
          fp16* __restrict__ Oh, fp16* __restrict__ Ol,
          float* __restrict__ Of,
          const float* __restrict__ bias, const void* __restrict__ mask,
          int lda, int ldb, int ldo, int K,
          long sA, long sB, long sO)
{
    extern __shared__ char smem[];
    const uint32_t sm0 = smem_u32(smem);

    constexpr uint32_t STAGE = 24576u;

    const int tid  = threadIdx.x;
    const int z    = blockIdx.z;
    const int mbase = blockIdx.y * 128;
    const int nbase = blockIdx.x * 128;

    Ap += (size_t)z * sA;
    Bh += (size_t)z * sB;  Bl += (size_t)z * sB;

    const int warp = tid >> 5;
    const int lane = tid & 31;
    const int wm = warp >> 1;          // 0..3 -> rows wm*32
    const int wn = warp & 1;           // 0..1 -> cols wn*64
    const int m8 = lane >> 3;
    const int l8 = lane & 7;

    const int C = K >> 5;

    auto issue = [&](int c) {
        const int s = c & 3;
        const uint32_t sb = sm0 + (uint32_t)s * STAGE;
        const size_t ka = (size_t)c * 32;
        {
            const fp16* ga = Ap + (size_t)mbase * lda + ka;
#pragma unroll
            for (int i = 0; i < 2; ++i) {
                int seg = tid + i * 256;          // 0..511
                int r = seg >> 2, cc = seg & 3;
                uint32_t sa = sb + r * 64 + ((cc ^ ((r >> 1) & 3)) << 4);
                cpa16(sa, ga + (size_t)r * lda + cc * 8);
            }
        }
        if (!BTRANS) {
            const fp16* gh = Bh + (size_t)nbase * ldb + ka;
            const fp16* gl = Bl + (size_t)nbase * ldb + ka;
#pragma unroll
            for (int i = 0; i < 2; ++i) {
                int seg = tid + i * 256;
                int r = seg >> 2, cc = seg & 3;
                uint32_t sa = sb + 8192 + r * 64 + ((cc ^ ((r >> 1) & 3)) << 4);
                cpa16(sa,        gh + (size_t)r * ldb + cc * 8);
                cpa16(sa + 8192, gl + (size_t)r * ldb + cc * 8);
            }
        } else {
            const fp16* gh = Bh + ka * ldb + nbase;
            const fp16* gl = Bl + ka * ldb + nbase;
#pragma unroll
            for (int i = 0; i < 2; ++i) {
                int seg = tid + i * 256;
                int k = seg >> 4, ns = seg & 15;
                uint32_t sa = sb + 8192 + k * 256 + ((ns ^ (k & 7)) << 4);
                cpa16(sa,        gh + (size_t)k * ldb + ns * 8);
                cpa16(sa + 8192, gl + (size_t)k * ldb + ns * 8);
            }
        }
    };

    issue(0); CP_COMMIT();
    issue(1); CP_COMMIT();
    issue(2); CP_COMMIT();

    float acc[2][8][4];
#pragma unroll
    for (int a = 0; a < 2; ++a)
#pragma unroll
        for (int b = 0; b < 8; ++b)
#pragma unroll
            for (int d = 0; d < 4; ++d) acc[a][b][d] = 0.0f;

    for (int c = 0; c < C; ++c) {
        CP_WAIT2();                 // stage c&3 resident
        __syncthreads();            // all warps done with stage (c-1)&3

        // refill the stage drained LAST iteration: (c+3)&3 == (c-1)&3
        if (c + 3 < C) issue(c + 3);
        CP_COMMIT();

        const uint32_t sb = sm0 + (uint32_t)(c & 3) * STAGE;

#pragma unroll
        for (int ks = 0; ks < 2; ++ks) {
            uint32_t ahf[2][4];
#pragma unroll
            for (int mt = 0; mt < 2; ++mt) {
                int r = wm * 32 + mt * 16 + (m8 & 1) * 8 + l8;
                int cA = 2 * ks + (m8 >> 1);
                uint32_t off = r * 64 + ((cA ^ ((r >> 1) & 3)) << 4);
                ldsm4(ahf[mt], sb + off);
            }
#pragma unroll
            for (int h2 = 0; h2 < 2; ++h2) {
                uint32_t bhf[2][4], blf[2][4];
#pragma unroll
                for (int gl = 0; gl < 2; ++gl) {
                    int g = h2 * 2 + gl;
                    if (!BTRANS) {
                        int n = wn * 64 + g * 16 + (m8 >> 1) * 8 + l8;
                        int cB = 2 * ks + (m8 & 1);
                        uint32_t off = n * 64 + ((cB ^ ((n >> 1) & 3)) << 4);
                        ldsm4(bhf[gl], sb + 8192 + off);
                        ldsm4(blf[gl], sb + 16384 + off);
                    } else {
                        int k = ks * 16 + (m8 & 1) * 8 + l8;
                        int ns = ((wn * 64 + g * 16) >> 3) + (m8 >> 1);
                        uint32_t off = k * 256 + ((ns ^ (k & 7)) << 4);
                        ldsm4t(bhf[gl], sb + 8192 + off);
                        ldsm4t(blf[gl], sb + 16384 + off);
                    }
                }
                // all hi products (8 independent accs), then all lo products:
                // no dependent back-to-back mma on the same accumulator.
#pragma unroll
                for (int mt = 0; mt < 2; ++mt)
#pragma unroll
                    for (int ntl = 0; ntl < 4; ++ntl)
                        mma16816(acc[mt][h2 * 4 + ntl], ahf[mt],
                                 &bhf[ntl >> 1][(ntl & 1) * 2]);
#pragma unroll
                for (int mt = 0; mt < 2; ++mt)
#pragma unroll
                    for (int ntl = 0; ntl < 4; ++ntl)
                        mma16816(acc[mt][h2 * 4 + ntl], ahf[mt],
                                 &blf[ntl >> 1][(ntl & 1) * 2]);
            }
        }
    }

    // ---------------- epilogue ------------------------------------------------
    const int rb = mbase + wm * 32 + (lane >> 2);
    const int cb = nbase + wn * 64 + (lane & 3) * 2;
    const int mode = (EPI == 1) ? g_mask_mode : 0;

    if (EPI == 0) { Oh += (size_t)z * sO; Ol += (size_t)z * sO; }
    if (EPI == 1 || EPI == 3) { Oh += (size_t)z * sO; }
    if (EPI == 2) { Of += (size_t)z * sO; }

#pragma unroll
    for (int mt = 0; mt < 2; ++mt)
#pragma unroll
        for (int h = 0; h < 2; ++h) {
            const int gr = rb + mt * 16 + h * 8;
#pragma unroll
            for (int nt = 0; nt < 8; ++nt) {
                const int gc = cb + nt * 8;
                float x0 = acc[mt][nt][h * 2 + 0];
                float x1 = acc[mt][nt][h * 2 + 1];

                if (EPI == 0 || EPI == 3) {
                    x0 += bias[gc];
                    x1 += bias[gc + 1];
                } else if (EPI == 1) {
                    int f0, f1;
                    const size_t mo = (size_t)z * ((size_t)LQn * LKn)
                                    + (size_t)gr * LKn + gc;
                    if (mode == 0) {
                        const unsigned char* mp = (const unsigned char*)mask + mo;
                        f0 = mp[0]; f1 = mp[1];
                    } else if (mode == 1) {
                        const int* mp = (const int*)mask + mo;
                        f0 = mp[0]; f1 = mp[1];
                    } else {
                        const float* mp = (const float*)mask + mo;
                        f0 = (mp[0] != 0.0f); f1 = (mp[1] != 0.0f);
                    }
                    x0 = f0 ? sigf(x0) : 0.0f;
                    x1 = f1 ? sigf(x1) : 0.0f;
                }

                if (EPI == 2) {
                    float2 p; p.x = x0; p.y = x1;
                    *reinterpret_cast<float2*>(Of + (size_t)gr * ldo + gc) = p;
                } else if (EPI == 1 || EPI == 3) {
                    __half2 ph = __halves2half2(__float2half_rn(x0),
                                                __float2half_rn(x1));
                    *reinterpret_cast<__half2*>(Oh + (size_t)gr * ldo + gc) = ph;
                } else {
                    fp16 h0 = __float2half_rn(x0), h1 = __float2half_rn(x1);
                    __half2 ph = __halves2half2(h0, h1);
                    __half2 pl = __halves2half2(
                        __float2half_rn(x0 - __half2float(h0)),
                        __float2half_rn(x1 - __half2float(h1)));
                    *reinterpret_cast<__half2*>(Oh + (size_t)gr * ldo + gc) = ph;
                    *reinterpret_cast<__half2*>(Ol + (size_t)gr * ldo + gc) = pl;
                }
            }
        }
}

// ---------------- host side ---------------------------------------------------
extern "C" void kernel_launch(void* const* d_in, const int* in_sizes, int n_in,
                              void* d_out, int out_size)
{
    const float* queries = (const float*)d_in[0];
    const float* values  = (const float*)d_in[1];
    const void*  mask    = d_in[2];
    const float* Wq = (const float*)d_in[3];
    const float* bq = (const float*)d_in[4];
    const float* Wk = (const float*)d_in[5];
    const float* bk = (const float*)d_in[6];
    const float* Wv = (const float*)d_in[7];
    const float* bv = (const float*)d_in[8];
    float* out = (float*)d_out;

    fp16 *q, *k_h, *k_l, *v_h, *v_l, *at, *qin, *vin;
    fp16 *wq_h, *wq_l, *wk_h, *wk_l, *wv_h, *wv_l;
    cudaGetSymbolAddress((void**)&qin, g_qin);
    cudaGetSymbolAddress((void**)&vin, g_vin);
    cudaGetSymbolAddress((void**)&wq_h, g_wq_h);
    cudaGetSymbolAddress((void**)&wq_l, g_wq_l);
    cudaGetSymbolAddress((void**)&wk_h, g_wk_h);
    cudaGetSymbolAddress((void**)&wk_l, g_wk_l);
    cudaGetSymbolAddress((void**)&wv_h, g_wv_h);
    cudaGetSymbolAddress((void**)&wv_l, g_wv_l);
    cudaGetSymbolAddress((void**)&q,   g_q);
    cudaGetSymbolAddress((void**)&k_h, g_k_h);
    cudaGetSymbolAddress((void**)&k_l, g_k_l);
    cudaGetSymbolAddress((void**)&v_h, g_v_h);
    cudaGetSymbolAddress((void**)&v_l, g_v_l);
    cudaGetSymbolAddress((void**)&at,  g_at);

    constexpr int SMEM = 4 * 24576;   // 96 KB
    static int attr_done = 0;
    if (!attr_done) {
        cudaFuncSetAttribute(gemm_fp16<0, false>,
                             cudaFuncAttributeMaxDynamicSharedMemorySize, SMEM);
        cudaFuncSetAttribute(gemm_fp16<3, false>,
                             cudaFuncAttributeMaxDynamicSharedMemorySize, SMEM);
        cudaFuncSetAttribute(gemm_fp16<1, false>,
                             cudaFuncAttributeMaxDynamicSharedMemorySize, SMEM);
        cudaFuncSetAttribute(gemm_fp16<2, true>,
                             cudaFuncAttributeMaxDynamicSharedMemorySize, SMEM);
        attr_done = 1;
    }

    // launch 1: mask dtype detection
    detect_mask_kernel<<<1, 256>>>((const unsigned*)mask, 8192);

    // launch 2: fused prep (converts + weight splits)
    {
        const int N4 = MR * Dn / 4, W4 = Dn * Dn / 4;
        const int total = 2 * N4 + 3 * W4;
        prep_kernel<<<(total + 255) / 256, 256>>>(queries, values, Wq, Wk, Wv);
    }

    // launch 3: q = queries @ Wq^T + bq -> single plane
    gemm_fp16<3, false><<<dim3(6, 128, 1), 256, SMEM>>>(
        qin, wq_h, wq_l, q, nullptr, nullptr, bq, nullptr,
        Dn, Dn, Dn, Dn, 0, 0, 0);
    // launch 4: v = values @ Wv^T + bv -> hi/lo
    gemm_fp16<0, false><<<dim3(6, 128, 1), 256, SMEM>>>(
        vin, wv_h, wv_l, v_h, v_l, nullptr, bv, nullptr,
        Dn, Dn, Dn, Dn, 0, 0, 0);
    // launch 5: k = v_hi @ Wk^T + bk -> hi/lo
    gemm_fp16<0, false><<<dim3(6, 128, 1), 256, SMEM>>>(
        v_h, wk_h, wk_l, k_h, k_l, nullptr, bk, nullptr,
        Dn, Dn, Dn, Dn, 0, 0, 0);
    // launch 6 (ncu -s 5 captures this): score
    gemm_fp16<1, false><<<dim3(16, 16, Bn), 256, SMEM>>>(
        q, k_h, k_l, at, nullptr, nullptr, nullptr, mask,
        Dn, Dn, LKn, Dn,
        (long)LQn * Dn, (long)LKn * Dn, (long)LQn * LKn);
    // launch 7: out = attn @ v (NN)
    gemm_fp16<2, true><<<dim3(6, 16, Bn), 256, SMEM>>>(
        at, v_h, v_l, nullptr, nullptr, out, nullptr, nullptr,
        LKn, Dn, Dn, LKn,
        (long)LQn * LKn, (long)LKn * Dn, (long)LQn * Dn);
}

// round 9
// speedup vs baseline: 1.8529x; 1.0065x over previous
#include <cuda_runtime.h>
#include <cuda_fp16.h>
#include <cstdint>
#include <cstddef>

// ============================================================================
// Problem: B=8, Lq=Lk=2048, D=768
//   q = queries@Wq^T+bq ; v = values@Wv^T+bv ; k = v@Wk^T+bk
//   attn = sigmoid(mask ? q@k^T : -1e9) ; out = attn@v
//
// Plain sm_100 target. mma.sync.m16n8k16.f32.f16.f16.f32 + ldmatrix + cp.async.
// Precision: A single fp16 plane, B hi/lo pair, acc += A*Bh + A*Bl.
// R9 vs R8 (1010us):
//  - score kernel prefetches its 128x128 byte-mask tile into smem via
//    cp.async bundled with chunk-0's commit group (epilogue mask loads were
//    serial scattered LDGs after the mainloop)
//  - q-proj and v-proj fused into one launch (grid.z selects) to share the
//    wave tail (each alone is 2.59 waves)
//  - mainloop untouched (measured tensor=55.5% matches the cycle model;
//    structural limit at 2 CTA/SM, 128 regs)
// ============================================================================

#define LQn 2048
#define LKn 2048
#define Dn  768
#define Bn  8
#define MR  (Bn * LQn)          // 16384

typedef __half fp16;

// ---------------- static device scratch (no cudaMalloc allowed) -------------
static __device__ fp16 g_qin[(size_t)MR * Dn];
static __device__ fp16 g_vin[(size_t)MR * Dn];
static __device__ fp16 g_wq_h[(size_t)Dn * Dn],  g_wq_l[(size_t)Dn * Dn];
static __device__ fp16 g_wk_h[(size_t)Dn * Dn],  g_wk_l[(size_t)Dn * Dn];
static __device__ fp16 g_wv_h[(size_t)Dn * Dn],  g_wv_l[(size_t)Dn * Dn];
static __device__ fp16 g_q[(size_t)MR * Dn];                       // hi only
static __device__ fp16 g_k_h[(size_t)MR * Dn],   g_k_l[(size_t)MR * Dn];
static __device__ fp16 g_v_h[(size_t)MR * Dn],   g_v_l[(size_t)MR * Dn];
static __device__ fp16 g_at[(size_t)Bn * LQn * LKn];               // single plane
static __device__ int  g_mask_mode;   // 0=byte, 1=int32, 2=float32

// ---------------- PTX helpers ------------------------------------------------
__device__ __forceinline__ uint32_t smem_u32(const void* p) {
    uint32_t a;
    asm("{ .reg .u64 t; cvta.to.shared.u64 t, %1; cvt.u32.u64 %0, t; }"
        : "=r"(a) : "l"(p));
    return a;
}

__device__ __forceinline__ void cpa16(uint32_t s, const void* g) {
    asm volatile("cp.async.cg.shared.global [%0], [%1], 16;"
                 :: "r"(s), "l"(g) : "memory");
}
#define CP_COMMIT() asm volatile("cp.async.commit_group;" ::: "memory")
#define CP_WAIT2()  asm volatile("cp.async.wait_group 2;"  ::: "memory")

__device__ __forceinline__ void ldsm4(uint32_t* r, uint32_t a) {
    asm volatile("ldmatrix.sync.aligned.m8n8.x4.shared.b16 {%0,%1,%2,%3}, [%4];"
                 : "=r"(r[0]), "=r"(r[1]), "=r"(r[2]), "=r"(r[3]) : "r"(a));
}
__device__ __forceinline__ void ldsm4t(uint32_t* r, uint32_t a) {
    asm volatile("ldmatrix.sync.aligned.m8n8.x4.trans.shared.b16 {%0,%1,%2,%3}, [%4];"
                 : "=r"(r[0]), "=r"(r[1]), "=r"(r[2]), "=r"(r[3]) : "r"(a));
}
__device__ __forceinline__ void mma16816(float* c, const uint32_t* a, const uint32_t* b) {
    asm volatile(
        "mma.sync.aligned.m16n8k16.row.col.f32.f16.f16.f32 "
        "{%0,%1,%2,%3}, {%4,%5,%6,%7}, {%8,%9}, {%0,%1,%2,%3};"
        : "+f"(c[0]), "+f"(c[1]), "+f"(c[2]), "+f"(c[3])
        : "r"(a[0]), "r"(a[1]), "r"(a[2]), "r"(a[3]), "r"(b[0]), "r"(b[1]));
}

__device__ __forceinline__ float sigf(float x) {
    return 1.0f / (1.0f + __expf(-x));
}

// ---------------- small kernels ----------------------------------------------
__global__ void detect_mask_kernel(const unsigned* __restrict__ w, int n) {
    int anyF = 0, anyO = 0;
    for (int i = threadIdx.x; i < n; i += blockDim.x) {
        unsigned x = w[i];
        anyF |= (x == 0x3F800000u);
        anyO |= (x != 0u && x != 1u && x != 0x3F800000u);
    }
    anyF = __syncthreads_or(anyF);
    anyO = __syncthreads_or(anyO);
    if (threadIdx.x == 0) g_mask_mode = anyF ? 2 : (anyO ? 0 : 1);
}

// Fused prep: convert queries/values -> fp16 plane; split Wq/Wk/Wv -> hi/lo.
__global__ void prep_kernel(const float* __restrict__ queries,
                            const float* __restrict__ values,
                            const float* __restrict__ Wq,
                            const float* __restrict__ Wk,
                            const float* __restrict__ Wv) {
    const int N4 = MR * Dn / 4;          // 3,145,728
    const int W4 = Dn * Dn / 4;          // 147,456
    int i = blockIdx.x * blockDim.x + threadIdx.x;

    const float* src;
    fp16 *dh, *dl = nullptr;
    int j = i;
    if (j < N4)                 { src = queries; dh = g_qin; }
    else if ((j -= N4) < N4)    { src = values;  dh = g_vin; }
    else if ((j -= N4) < W4)    { src = Wq; dh = g_wq_h; dl = g_wq_l; }
    else if ((j -= W4) < W4)    { src = Wk; dh = g_wk_h; dl = g_wk_l; }
    else if ((j -= W4) < W4)    { src = Wv; dh = g_wv_h; dl = g_wv_l; }
    else return;

    float4 x = reinterpret_cast<const float4*>(src)[j];
    fp16 h0 = __float2half_rn(x.x), h1 = __float2half_rn(x.y);
    fp16 h2 = __float2half_rn(x.z), h3 = __float2half_rn(x.w);
    reinterpret_cast<__half2*>(dh)[j * 2 + 0] = __halves2half2(h0, h1);
    reinterpret_cast<__half2*>(dh)[j * 2 + 1] = __halves2half2(h2, h3);
    if (dl) {
        __half2 l0 = __halves2half2(__float2half_rn(x.x - __half2float(h0)),
                                    __float2half_rn(x.y - __half2float(h1)));
        __half2 l1 = __halves2half2(__float2half_rn(x.z - __half2float(h2)),
                                    __float2half_rn(x.w - __half2float(h3)));
        reinterpret_cast<__half2*>(dl)[j * 2 + 0] = l0;
        reinterpret_cast<__half2*>(dl)[j * 2 + 1] = l1;
    }
}

// ---------------- GEMM body ---------------------------------------------------
// CTA tile 128x128, BK=32, 8 warps (warp tile 32x64), 4 stage buffers with
// 3 cp.async groups in flight, ONE __syncthreads per chunk, 2 CTAs/SM.
// A single plane; B hi/lo pair; acc += A*Bh + A*Bl (bH batch then bL batch).
// EPI: 0 = +bias, store fp16 hi/lo | 1 = mask+sigmoid, store fp16 single
//      | 2 = plain fp32 store | 3 = +bias, store fp16 single.
// Stage layout (24 KB): A@0  Bh@8K  Bl@16K.  EPI1: mask tile @ 96K (16 KB).
// A-type tile: 128 rows x 32 k fp16, 64 B/row: addr = r*64 + (c ^ ((r>>1)&3))*16
// B NN tile:   32 k x 128 n fp16, 256 B/row:  addr = k*256 + (ns ^ (k&7))*16

template<int EPI, bool BTRANS>
__device__ __forceinline__ void
gemm_body(char* smem, uint32_t sm0,
          const fp16* __restrict__ Ap, const fp16* __restrict__ Bh,
          const fp16* __restrict__ Bl,
          fp16* __restrict__ Oh, fp16* __restrict__ Ol,
          float* __restrict__ Of,
          const float* __restrict__ bias, const void* __restrict__ mask,
          int lda, int ldb, int ldo, int K,
          long sA, long sB, long sO,
          int z, int mbase, int nbase)
{
    constexpr uint32_t STAGE = 24576u;
    constexpr uint32_t MASKOFF = 4u * STAGE;     // 98304

    const int tid  = threadIdx.x;

    Ap += (size_t)z * sA;
    Bh += (size_t)z * sB;  Bl += (size_t)z * sB;

    const int warp = tid >> 5;
    const int lane = tid & 31;
    const int wm = warp >> 1;          // 0..3 -> rows wm*32
    const int wn = warp & 1;           // 0..1 -> cols wn*64
    const int m8 = lane >> 3;
    const int l8 = lane & 7;

    const int C = K >> 5;
    const int mode = (EPI == 1) ? g_mask_mode : 0;

    auto issue = [&](int c) {
        const int s = c & 3;
        const uint32_t sb = sm0 + (uint32_t)s * STAGE;
        const size_t ka = (size_t)c * 32;
        {
            const fp16* ga = Ap + (size_t)mbase * lda + ka;
#pragma unroll
            for (int i = 0; i < 2; ++i) {
                int seg = tid + i * 256;          // 0..511
                int r = seg >> 2, cc = seg & 3;
                uint32_t sa = sb + r * 64 + ((cc ^ ((r >> 1) & 3)) << 4);
                cpa16(sa, ga + (size_t)r * lda + cc * 8);
            }
        }
        if (!BTRANS) {
            const fp16* gh = Bh + (size_t)nbase * ldb + ka;
            const fp16* gl = Bl + (size_t)nbase * ldb + ka;
#pragma unroll
            for (int i = 0; i < 2; ++i) {
                int seg = tid + i * 256;
                int r = seg >> 2, cc = seg & 3;
                uint32_t sa = sb + 8192 + r * 64 + ((cc ^ ((r >> 1) & 3)) << 4);
                cpa16(sa,        gh + (size_t)r * ldb + cc * 8);
                cpa16(sa + 8192, gl + (size_t)r * ldb + cc * 8);
            }
        } else {
            const fp16* gh = Bh + ka * ldb + nbase;
            const fp16* gl = Bl + ka * ldb + nbase;
#pragma unroll
            for (int i = 0; i < 2; ++i) {
                int seg = tid + i * 256;
                int k = seg >> 4, ns = seg & 15;
                uint32_t sa = sb + 8192 + k * 256 + ((ns ^ (k & 7)) << 4);
                cpa16(sa,        gh + (size_t)k * ldb + ns * 8);
                cpa16(sa + 8192, gl + (size_t)k * ldb + ns * 8);
            }
        }
    };

    // EPI1 byte-mask: prefetch the CTA's 128x128-byte mask tile with group 0.
    if (EPI == 1 && mode == 0) {
        const unsigned char* mp = (const unsigned char*)mask
            + (size_t)z * ((size_t)LQn * LKn) + (size_t)mbase * LKn + nbase;
#pragma unroll
        for (int i = 0; i < 4; ++i) {
            int seg = tid + i * 256;              // 0..1023
            int r = seg >> 3, cc = seg & 7;       // 128 rows x 8 x16B
            cpa16(sm0 + MASKOFF + r * 128 + cc * 16,
                  mp + (size_t)r * LKn + cc * 16);
        }
    }
    issue(0); CP_COMMIT();
    issue(1); CP_COMMIT();
    issue(2); CP_COMMIT();

    float acc[2][8][4];
#pragma unroll
    for (int a = 0; a < 2; ++a)
#pragma unroll
        for (int b = 0; b < 8; ++b)
#pragma unroll
            for (int d = 0; d < 4; ++d) acc[a][b][d] = 0.0f;

    for (int c = 0; c < C; ++c) {
        CP_WAIT2();                 // stage c&3 resident
        __syncthreads();            // all warps done with stage (c-1)&3

        // refill the stage drained LAST iteration: (c+3)&3 == (c-1)&3
        if (c + 3 < C) issue(c + 3);
        CP_COMMIT();

        const uint32_t sb = sm0 + (uint32_t)(c & 3) * STAGE;

#pragma unroll
        for (int ks = 0; ks < 2; ++ks) {
            uint32_t ahf[2][4];
#pragma unroll
            for (int mt = 0; mt < 2; ++mt) {
                int r = wm * 32 + mt * 16 + (m8 & 1) * 8 + l8;
                int cA = 2 * ks + (m8 >> 1);
                uint32_t off = r * 64 + ((cA ^ ((r >> 1) & 3)) << 4);
                ldsm4(ahf[mt], sb + off);
            }
#pragma unroll
            for (int h2 = 0; h2 < 2; ++h2) {
                uint32_t bhf[2][4], blf[2][4];
#pragma unroll
                for (int gl = 0; gl < 2; ++gl) {
                    int g = h2 * 2 + gl;
                    if (!BTRANS) {
                        int n = wn * 64 + g * 16 + (m8 >> 1) * 8 + l8;
                        int cB = 2 * ks + (m8 & 1);
                        uint32_t off = n * 64 + ((cB ^ ((n >> 1) & 3)) << 4);
                        ldsm4(bhf[gl], sb + 8192 + off);
                        ldsm4(blf[gl], sb + 16384 + off);
                    } else {
                        int k = ks * 16 + (m8 & 1) * 8 + l8;
                        int ns = ((wn * 64 + g * 16) >> 3) + (m8 >> 1);
                        uint32_t off = k * 256 + ((ns ^ (k & 7)) << 4);
                        ldsm4t(bhf[gl], sb + 8192 + off);
                        ldsm4t(blf[gl], sb + 16384 + off);
                    }
                }
                // all hi products (8 independent accs), then all lo products.
#pragma unroll
                for (int mt = 0; mt < 2; ++mt)
#pragma unroll
                    for (int ntl = 0; ntl < 4; ++ntl)
                        mma16816(acc[mt][h2 * 4 + ntl], ahf[mt],
                                 &bhf[ntl >> 1][(ntl & 1) * 2]);
#pragma unroll
                for (int mt = 0; mt < 2; ++mt)
#pragma unroll
                    for (int ntl = 0; ntl < 4; ++ntl)
                        mma16816(acc[mt][h2 * 4 + ntl], ahf[mt],
                                 &blf[ntl >> 1][(ntl & 1) * 2]);
            }
        }
    }

    // ---------------- epilogue ------------------------------------------------
    const int rb = mbase + wm * 32 + (lane >> 2);
    const int cb = nbase + wn * 64 + (lane & 3) * 2;

    if (EPI == 0) { Oh += (size_t)z * sO; Ol += (size_t)z * sO; }
    if (EPI == 1 || EPI == 3) { Oh += (size_t)z * sO; }
    if (EPI == 2) { Of += (size_t)z * sO; }

#pragma unroll
    for (int mt = 0; mt < 2; ++mt)
#pragma unroll
        for (int h = 0; h < 2; ++h) {
            const int gr = rb + mt * 16 + h * 8;
#pragma unroll
            for (int nt = 0; nt < 8; ++nt) {
                const int gc = cb + nt * 8;
                float x0 = acc[mt][nt][h * 2 + 0];
                float x1 = acc[mt][nt][h * 2 + 1];

                if (EPI == 0 || EPI == 3) {
                    x0 += bias[gc];
                    x1 += bias[gc + 1];
                } else if (EPI == 1) {
                    int f0, f1;
                    if (mode == 0) {
                        // prefetched smem tile (completed with cp group 0;
                        // every thread has passed several __syncthreads since)
                        const unsigned char* ms = (const unsigned char*)smem
                            + MASKOFF + (size_t)(gr - mbase) * 128 + (gc - nbase);
                        f0 = ms[0]; f1 = ms[1];
                    } else {
                        const size_t mo = (size_t)z * ((size_t)LQn * LKn)
                                        + (size_t)gr * LKn + gc;
                        if (mode == 1) {
                            const int* mp = (const int*)mask + mo;
                            f0 = mp[0]; f1 = mp[1];
                        } else {
                            const float* mp = (const float*)mask + mo;
                            f0 = (mp[0] != 0.0f); f1 = (mp[1] != 0.0f);
                        }
                    }
                    x0 = f0 ? sigf(x0) : 0.0f;
                    x1 = f1 ? sigf(x1) : 0.0f;
                }

                if (EPI == 2) {
                    float2 p; p.x = x0; p.y = x1;
                    *reinterpret_cast<float2*>(Of + (size_t)gr * ldo + gc) = p;
                } else if (EPI == 1 || EPI == 3) {
                    __half2 ph = __halves2half2(__float2half_rn(x0),
                                                __float2half_rn(x1));
                    *reinterpret_cast<__half2*>(Oh + (size_t)gr * ldo + gc) = ph;
                } else {
                    fp16 h0 = __float2half_rn(x0), h1 = __float2half_rn(x1);
                    __half2 ph = __halves2half2(h0, h1);
                    __half2 pl = __halves2half2(
                        __float2half_rn(x0 - __half2float(h0)),
                        __float2half_rn(x1 - __half2float(h1)));
                    *reinterpret_cast<__half2*>(Oh + (size_t)gr * ldo + gc) = ph;
                    *reinterpret_cast<__half2*>(Ol + (size_t)gr * ldo + gc) = pl;
                }
            }
        }
}

// ---------------- kernels -----------------------------------------------------
template<int EPI, bool BTRANS>
__global__ void __launch_bounds__(256, 2)
gemm_fp16(const fp16* __restrict__ Ap, const fp16* __restrict__ Bh,
          const fp16* __restrict__ Bl,
          fp16* __restrict__ Oh, fp16* __restrict__ Ol,
          float* __restrict__ Of,
          const float* __restrict__ bias, const void* __restrict__ mask,
          int lda, int ldb, int ldo, int K,
          long sA, long sB, long sO)
{
    extern __shared__ char smem[];
    gemm_body<EPI, BTRANS>(smem, smem_u32(smem),
                           Ap, Bh, Bl, Oh, Ol, Of, bias, mask,
                           lda, ldb, ldo, K, sA, sB, sO,
                           blockIdx.z, blockIdx.y * 128, blockIdx.x * 128);
}

// Fused q-proj (z==0, EPI3) + v-proj (z==1, EPI0); both NT, batch=1.
__global__ void __launch_bounds__(256, 2)
proj_dual(const fp16* __restrict__ qin,
          const fp16* __restrict__ wqh, const fp16* __restrict__ wql,
          fp16* __restrict__ qo, const float* __restrict__ bq,
          const fp16* __restrict__ vin,
          const fp16* __restrict__ wvh, const fp16* __restrict__ wvl,
          fp16* __restrict__ vh, fp16* __restrict__ vl,
          const float* __restrict__ bv)
{
    extern __shared__ char smem[];
    const uint32_t sm0 = smem_u32(smem);
    const int mb = blockIdx.y * 128, nb = blockIdx.x * 128;
    if (blockIdx.z == 0)
        gemm_body<3, false>(smem, sm0, qin, wqh, wql, qo, nullptr, nullptr,
                            bq, nullptr, Dn, Dn, Dn, Dn, 0, 0, 0, 0, mb, nb);
    else
        gemm_body<0, false>(smem, sm0, vin, wvh, wvl, vh, vl, nullptr,
                            bv, nullptr, Dn, Dn, Dn, Dn, 0, 0, 0, 0, mb, nb);
}

// ---------------- host side ---------------------------------------------------
extern "C" void kernel_launch(void* const* d_in, const int* in_sizes, int n_in,
                              void* d_out, int out_size)
{
    const float* queries = (const float*)d_in[0];
    const float* values  = (const float*)d_in[1];
    const void*  mask    = d_in[2];
    const float* Wq = (const float*)d_in[3];
    const float* bq = (const float*)d_in[4];
    const float* Wk = (const float*)d_in[5];
    const float* bk = (const float*)d_in[6];
    const float* Wv = (const float*)d_in[7];
    const float* bv = (const float*)d_in[8];
    float* out = (float*)d_out;

    fp16 *q, *k_h, *k_l, *v_h, *v_l, *at, *qin, *vin;
    fp16 *wq_h, *wq_l, *wk_h, *wk_l, *wv_h, *wv_l;
    cudaGetSymbolAddress((void**)&qin, g_qin);
    cudaGetSymbolAddress((void**)&vin, g_vin);
    cudaGetSymbolAddress((void**)&wq_h, g_wq_h);
    cudaGetSymbolAddress((void**)&wq_l, g_wq_l);
    cudaGetSymbolAddress((void**)&wk_h, g_wk_h);
    cudaGetSymbolAddress((void**)&wk_l, g_wk_l);
    cudaGetSymbolAddress((void**)&wv_h, g_wv_h);
    cudaGetSymbolAddress((void**)&wv_l, g_wv_l);
    cudaGetSymbolAddress((void**)&q,   g_q);
    cudaGetSymbolAddress((void**)&k_h, g_k_h);
    cudaGetSymbolAddress((void**)&k_l, g_k_l);
    cudaGetSymbolAddress((void**)&v_h, g_v_h);
    cudaGetSymbolAddress((void**)&v_l, g_v_l);
    cudaGetSymbolAddress((void**)&at,  g_at);

    constexpr int SMEM   = 4 * 24576;            // 96 KB
    constexpr int SMEM_M = 4 * 24576 + 16384;    // 112 KB (score: +mask tile)
    static int attr_done = 0;
    if (!attr_done) {
        cudaFuncSetAttribute(proj_dual,
                             cudaFuncAttributeMaxDynamicSharedMemorySize, SMEM);
        cudaFuncSetAttribute(gemm_fp16<0, false>,
                             cudaFuncAttributeMaxDynamicSharedMemorySize, SMEM);
        cudaFuncSetAttribute(gemm_fp16<1, false>,
                             cudaFuncAttributeMaxDynamicSharedMemorySize, SMEM_M);
        cudaFuncSetAttribute(gemm_fp16<2, true>,
                             cudaFuncAttributeMaxDynamicSharedMemorySize, SMEM);
        attr_done = 1;
    }

    // launch 1: mask dtype detection
    detect_mask_kernel<<<1, 256>>>((const unsigned*)mask, 8192);

    // launch 2: fused prep (converts + weight splits)
    {
        const int N4 = MR * Dn / 4, W4 = Dn * Dn / 4;
        const int total = 2 * N4 + 3 * W4;
        prep_kernel<<<(total + 255) / 256, 256>>>(queries, values, Wq, Wk, Wv);
    }

    // launch 3: fused q-proj + v-proj (independent; shared wave tail)
    proj_dual<<<dim3(6, 128, 2), 256, SMEM>>>(
        qin, wq_h, wq_l, q, bq, vin, wv_h, wv_l, v_h, v_l, bv);

    // launch 4: k = v_hi @ Wk^T + bk -> hi/lo
    gemm_fp16<0, false><<<dim3(6, 128, 1), 256, SMEM>>>(
        v_h, wk_h, wk_l, k_h, k_l, nullptr, bk, nullptr,
        Dn, Dn, Dn, Dn, 0, 0, 0);

    // launch 5: score = sigmoid(mask ? q@k^T : -1e9), mask tile in smem
    gemm_fp16<1, false><<<dim3(16, 16, Bn), 256, SMEM_M>>>(
        q, k_h, k_l, at, nullptr, nullptr, nullptr, mask,
        Dn, Dn, LKn, Dn,
        (long)LQn * Dn, (long)LKn * Dn, (long)LQn * LKn);

    // launch 6: out = attn @ v (NN)
    gemm_fp16<2, true><<<dim3(6, 16, Bn), 256, SMEM>>>(
        at, v_h, v_l, nullptr, nullptr, out, nullptr, nullptr,
        LKn, Dn, Dn, LKn,
        (long)LQn * LKn, (long)LKn * Dn, (long)LQn * Dn);
}

// round 10
// speedup vs baseline: 2.0971x; 1.1318x over previous
#include <cuda_runtime.h>
#include <cuda_fp16.h>
#include <cstdint>
#include <cstddef>

// ============================================================================
// Problem: B=8, Lq=Lk=2048, D=768
//   q = queries@Wq^T+bq ; v = values@Wv^T+bv ; k = v@Wk^T+bk
//   attn = sigmoid(mask ? q@k^T : -1e9) ; out = attn@v
//
// Plain sm_100 target. mma.sync.m16n8k16.f32.f16.f16.f32 + ldmatrix + cp.async.
// Precision: A single fp16 plane everywhere. Score path keeps B (weights, k)
// as hi/lo pairs (2 products). Context GEMM is 1-product: v stored single
// fp16 plane (empirically-anchored predicted rel_err ~6.1e-4 < 1e-3).
// R10 vs R9 (1003.6us): context BSINGLE path (half B traffic/ldsm/mma),
// v-proj stores single plane. Mainloop/tiling untouched.
// ============================================================================

#define LQn 2048
#define LKn 2048
#define Dn  768
#define Bn  8
#define MR  (Bn * LQn)          // 16384

typedef __half fp16;

// ---------------- static device scratch (no cudaMalloc allowed) -------------
static __device__ fp16 g_qin[(size_t)MR * Dn];
static __device__ fp16 g_vin[(size_t)MR * Dn];
static __device__ fp16 g_wq_h[(size_t)Dn * Dn],  g_wq_l[(size_t)Dn * Dn];
static __device__ fp16 g_wk_h[(size_t)Dn * Dn],  g_wk_l[(size_t)Dn * Dn];
static __device__ fp16 g_wv_h[(size_t)Dn * Dn],  g_wv_l[(size_t)Dn * Dn];
static __device__ fp16 g_q[(size_t)MR * Dn];                       // hi only
static __device__ fp16 g_k_h[(size_t)MR * Dn],   g_k_l[(size_t)MR * Dn];
static __device__ fp16 g_v[(size_t)MR * Dn];                       // single plane
static __device__ fp16 g_at[(size_t)Bn * LQn * LKn];               // single plane
static __device__ int  g_mask_mode;   // 0=byte, 1=int32, 2=float32

// ---------------- PTX helpers ------------------------------------------------
__device__ __forceinline__ uint32_t smem_u32(const void* p) {
    uint32_t a;
    asm("{ .reg .u64 t; cvta.to.shared.u64 t, %1; cvt.u32.u64 %0, t; }"
        : "=r"(a) : "l"(p));
    return a;
}

__device__ __forceinline__ void cpa16(uint32_t s, const void* g) {
    asm volatile("cp.async.cg.shared.global [%0], [%1], 16;"
                 :: "r"(s), "l"(g) : "memory");
}
#define CP_COMMIT() asm volatile("cp.async.commit_group;" ::: "memory")
#define CP_WAIT2()  asm volatile("cp.async.wait_group 2;"  ::: "memory")

__device__ __forceinline__ void ldsm4(uint32_t* r, uint32_t a) {
    asm volatile("ldmatrix.sync.aligned.m8n8.x4.shared.b16 {%0,%1,%2,%3}, [%4];"
                 : "=r"(r[0]), "=r"(r[1]), "=r"(r[2]), "=r"(r[3]) : "r"(a));
}
__device__ __forceinline__ void ldsm4t(uint32_t* r, uint32_t a) {
    asm volatile("ldmatrix.sync.aligned.m8n8.x4.trans.shared.b16 {%0,%1,%2,%3}, [%4];"
                 : "=r"(r[0]), "=r"(r[1]), "=r"(r[2]), "=r"(r[3]) : "r"(a));
}
__device__ __forceinline__ void mma16816(float* c, const uint32_t* a, const uint32_t* b) {
    asm volatile(
        "mma.sync.aligned.m16n8k16.row.col.f32.f16.f16.f32 "
        "{%0,%1,%2,%3}, {%4,%5,%6,%7}, {%8,%9}, {%0,%1,%2,%3};"
        : "+f"(c[0]), "+f"(c[1]), "+f"(c[2]), "+f"(c[3])
        : "r"(a[0]), "r"(a[1]), "r"(a[2]), "r"(a[3]), "r"(b[0]), "r"(b[1]));
}

__device__ __forceinline__ float sigf(float x) {
    return 1.0f / (1.0f + __expf(-x));
}

// ---------------- small kernels ----------------------------------------------
__global__ void detect_mask_kernel(const unsigned* __restrict__ w, int n) {
    int anyF = 0, anyO = 0;
    for (int i = threadIdx.x; i < n; i += blockDim.x) {
        unsigned x = w[i];
        anyF |= (x == 0x3F800000u);
        anyO |= (x != 0u && x != 1u && x != 0x3F800000u);
    }
    anyF = __syncthreads_or(anyF);
    anyO = __syncthreads_or(anyO);
    if (threadIdx.x == 0) g_mask_mode = anyF ? 2 : (anyO ? 0 : 1);
}

// Fused prep: convert queries/values -> fp16 plane; split Wq/Wk/Wv -> hi/lo.
__global__ void prep_kernel(const float* __restrict__ queries,
                            const float* __restrict__ values,
                            const float* __restrict__ Wq,
                            const float* __restrict__ Wk,
                            const float* __restrict__ Wv) {
    const int N4 = MR * Dn / 4;          // 3,145,728
    const int W4 = Dn * Dn / 4;          // 147,456
    int i = blockIdx.x * blockDim.x + threadIdx.x;

    const float* src;
    fp16 *dh, *dl = nullptr;
    int j = i;
    if (j < N4)                 { src = queries; dh = g_qin; }
    else if ((j -= N4) < N4)    { src = values;  dh = g_vin; }
    else if ((j -= N4) < W4)    { src = Wq; dh = g_wq_h; dl = g_wq_l; }
    else if ((j -= W4) < W4)    { src = Wk; dh = g_wk_h; dl = g_wk_l; }
    else if ((j -= W4) < W4)    { src = Wv; dh = g_wv_h; dl = g_wv_l; }
    else return;

    float4 x = reinterpret_cast<const float4*>(src)[j];
    fp16 h0 = __float2half_rn(x.x), h1 = __float2half_rn(x.y);
    fp16 h2 = __float2half_rn(x.z), h3 = __float2half_rn(x.w);
    reinterpret_cast<__half2*>(dh)[j * 2 + 0] = __halves2half2(h0, h1);
    reinterpret_cast<__half2*>(dh)[j * 2 + 1] = __halves2half2(h2, h3);
    if (dl) {
        __half2 l0 = __halves2half2(__float2half_rn(x.x - __half2float(h0)),
                                    __float2half_rn(x.y - __half2float(h1)));
        __half2 l1 = __halves2half2(__float2half_rn(x.z - __half2float(h2)),
                                    __float2half_rn(x.w - __half2float(h3)));
        reinterpret_cast<__half2*>(dl)[j * 2 + 0] = l0;
        reinterpret_cast<__half2*>(dl)[j * 2 + 1] = l1;
    }
}

// ---------------- GEMM body ---------------------------------------------------
// CTA tile 128x128, BK=32, 8 warps (warp tile 32x64), 4 stage buffers with
// 3 cp.async groups in flight, ONE __syncthreads per chunk, 2 CTAs/SM.
// BSINGLE=false: B hi/lo pair, acc += A*Bh + A*Bl.
// BSINGLE=true : B single plane, acc += A*Bh (half ldsm/mma/traffic).
// EPI: 0 = +bias, store fp16 hi/lo | 1 = mask+sigmoid, store fp16 single
//      | 2 = plain fp32 store | 3 = +bias, store fp16 single.
// Stage layout (24 KB): A@0  Bh@8K  Bl@16K.  EPI1: mask tile @ 96K (16 KB).
// A-type tile: 128 rows x 32 k fp16, 64 B/row: addr = r*64 + (c ^ ((r>>1)&3))*16
// B NN tile:   32 k x 128 n fp16, 256 B/row:  addr = k*256 + (ns ^ (k&7))*16

template<int EPI, bool BTRANS, bool BSINGLE>
__device__ __forceinline__ void
gemm_body(char* smem, uint32_t sm0,
          const fp16* __restrict__ Ap, const fp16* __restrict__ Bh,
          const fp16* __restrict__ Bl,
          fp16* __restrict__ Oh, fp16* __restrict__ Ol,
          float* __restrict__ Of,
          const float* __restrict__ bias, const void* __restrict__ mask,
          int lda, int ldb, int ldo, int K,
          long sA, long sB, long sO,
          int z, int mbase, int nbase)
{
    constexpr uint32_t STAGE = 24576u;
    constexpr uint32_t MASKOFF = 4u * STAGE;     // 98304

    const int tid  = threadIdx.x;

    Ap += (size_t)z * sA;
    Bh += (size_t)z * sB;
    if (!BSINGLE) Bl += (size_t)z * sB;

    const int warp = tid >> 5;
    const int lane = tid & 31;
    const int wm = warp >> 1;          // 0..3 -> rows wm*32
    const int wn = warp & 1;           // 0..1 -> cols wn*64
    const int m8 = lane >> 3;
    const int l8 = lane & 7;

    const int C = K >> 5;
    const int mode = (EPI == 1) ? g_mask_mode : 0;

    auto issue = [&](int c) {
        const int s = c & 3;
        const uint32_t sb = sm0 + (uint32_t)s * STAGE;
        const size_t ka = (size_t)c * 32;
        {
            const fp16* ga = Ap + (size_t)mbase * lda + ka;
#pragma unroll
            for (int i = 0; i < 2; ++i) {
                int seg = tid + i * 256;          // 0..511
                int r = seg >> 2, cc = seg & 3;
                uint32_t sa = sb + r * 64 + ((cc ^ ((r >> 1) & 3)) << 4);
                cpa16(sa, ga + (size_t)r * lda + cc * 8);
            }
        }
        if (!BTRANS) {
            const fp16* gh = Bh + (size_t)nbase * ldb + ka;
            const fp16* gl = BSINGLE ? nullptr : (Bl + (size_t)nbase * ldb + ka);
#pragma unroll
            for (int i = 0; i < 2; ++i) {
                int seg = tid + i * 256;
                int r = seg >> 2, cc = seg & 3;
                uint32_t sa = sb + 8192 + r * 64 + ((cc ^ ((r >> 1) & 3)) << 4);
                cpa16(sa, gh + (size_t)r * ldb + cc * 8);
                if (!BSINGLE) cpa16(sa + 8192, gl + (size_t)r * ldb + cc * 8);
            }
        } else {
            const fp16* gh = Bh + ka * ldb + nbase;
            const fp16* gl = BSINGLE ? nullptr : (Bl + ka * ldb + nbase);
#pragma unroll
            for (int i = 0; i < 2; ++i) {
                int seg = tid + i * 256;
                int k = seg >> 4, ns = seg & 15;
                uint32_t sa = sb + 8192 + k * 256 + ((ns ^ (k & 7)) << 4);
                cpa16(sa, gh + (size_t)k * ldb + ns * 8);
                if (!BSINGLE) cpa16(sa + 8192, gl + (size_t)k * ldb + ns * 8);
            }
        }
    };

    // EPI1 byte-mask: prefetch the CTA's 128x128-byte mask tile with group 0.
    if (EPI == 1 && mode == 0) {
        const unsigned char* mp = (const unsigned char*)mask
            + (size_t)z * ((size_t)LQn * LKn) + (size_t)mbase * LKn + nbase;
#pragma unroll
        for (int i = 0; i < 4; ++i) {
            int seg = tid + i * 256;              // 0..1023
            int r = seg >> 3, cc = seg & 7;       // 128 rows x 8 x16B
            cpa16(sm0 + MASKOFF + r * 128 + cc * 16,
                  mp + (size_t)r * LKn + cc * 16);
        }
    }
    issue(0); CP_COMMIT();
    issue(1); CP_COMMIT();
    issue(2); CP_COMMIT();

    float acc[2][8][4];
#pragma unroll
    for (int a = 0; a < 2; ++a)
#pragma unroll
        for (int b = 0; b < 8; ++b)
#pragma unroll
            for (int d = 0; d < 4; ++d) acc[a][b][d] = 0.0f;

    for (int c = 0; c < C; ++c) {
        CP_WAIT2();                 // stage c&3 resident
        __syncthreads();            // all warps done with stage (c-1)&3

        // refill the stage drained LAST iteration: (c+3)&3 == (c-1)&3
        if (c + 3 < C) issue(c + 3);
        CP_COMMIT();

        const uint32_t sb = sm0 + (uint32_t)(c & 3) * STAGE;

#pragma unroll
        for (int ks = 0; ks < 2; ++ks) {
            uint32_t ahf[2][4];
#pragma unroll
            for (int mt = 0; mt < 2; ++mt) {
                int r = wm * 32 + mt * 16 + (m8 & 1) * 8 + l8;
                int cA = 2 * ks + (m8 >> 1);
                uint32_t off = r * 64 + ((cA ^ ((r >> 1) & 3)) << 4);
                ldsm4(ahf[mt], sb + off);
            }
#pragma unroll
            for (int h2 = 0; h2 < 2; ++h2) {
                uint32_t bhf[2][4], blf[2][4];
#pragma unroll
                for (int gl = 0; gl < 2; ++gl) {
                    int g = h2 * 2 + gl;
                    if (!BTRANS) {
                        int n = wn * 64 + g * 16 + (m8 >> 1) * 8 + l8;
                        int cB = 2 * ks + (m8 & 1);
                        uint32_t off = n * 64 + ((cB ^ ((n >> 1) & 3)) << 4);
                        ldsm4(bhf[gl], sb + 8192 + off);
                        if (!BSINGLE) ldsm4(blf[gl], sb + 16384 + off);
                    } else {
                        int k = ks * 16 + (m8 & 1) * 8 + l8;
                        int ns = ((wn * 64 + g * 16) >> 3) + (m8 >> 1);
                        uint32_t off = k * 256 + ((ns ^ (k & 7)) << 4);
                        ldsm4t(bhf[gl], sb + 8192 + off);
                        if (!BSINGLE) ldsm4t(blf[gl], sb + 16384 + off);
                    }
                }
                // all hi products (8 independent accs), then all lo products.
#pragma unroll
                for (int mt = 0; mt < 2; ++mt)
#pragma unroll
                    for (int ntl = 0; ntl < 4; ++ntl)
                        mma16816(acc[mt][h2 * 4 + ntl], ahf[mt],
                                 &bhf[ntl >> 1][(ntl & 1) * 2]);
                if (!BSINGLE) {
#pragma unroll
                    for (int mt = 0; mt < 2; ++mt)
#pragma unroll
                        for (int ntl = 0; ntl < 4; ++ntl)
                            mma16816(acc[mt][h2 * 4 + ntl], ahf[mt],
                                     &blf[ntl >> 1][(ntl & 1) * 2]);
                }
            }
        }
    }

    // ---------------- epilogue ------------------------------------------------
    const int rb = mbase + wm * 32 + (lane >> 2);
    const int cb = nbase + wn * 64 + (lane & 3) * 2;

    if (EPI == 0) { Oh += (size_t)z * sO; Ol += (size_t)z * sO; }
    if (EPI == 1 || EPI == 3) { Oh += (size_t)z * sO; }
    if (EPI == 2) { Of += (size_t)z * sO; }

#pragma unroll
    for (int mt = 0; mt < 2; ++mt)
#pragma unroll
        for (int h = 0; h < 2; ++h) {
            const int gr = rb + mt * 16 + h * 8;
#pragma unroll
            for (int nt = 0; nt < 8; ++nt) {
                const int gc = cb + nt * 8;
                float x0 = acc[mt][nt][h * 2 + 0];
                float x1 = acc[mt][nt][h * 2 + 1];

                if (EPI == 0 || EPI == 3) {
                    x0 += bias[gc];
                    x1 += bias[gc + 1];
                } else if (EPI == 1) {
                    int f0, f1;
                    if (mode == 0) {
                        const unsigned char* ms = (const unsigned char*)smem
                            + MASKOFF + (size_t)(gr - mbase) * 128 + (gc - nbase);
                        f0 = ms[0]; f1 = ms[1];
                    } else {
                        const size_t mo = (size_t)z * ((size_t)LQn * LKn)
                                        + (size_t)gr * LKn + gc;
                        if (mode == 1) {
                            const int* mp = (const int*)mask + mo;
                            f0 = mp[0]; f1 = mp[1];
                        } else {
                            const float* mp = (const float*)mask + mo;
                            f0 = (mp[0] != 0.0f); f1 = (mp[1] != 0.0f);
                        }
                    }
                    x0 = f0 ? sigf(x0) : 0.0f;
                    x1 = f1 ? sigf(x1) : 0.0f;
                }

                if (EPI == 2) {
                    float2 p; p.x = x0; p.y = x1;
                    *reinterpret_cast<float2*>(Of + (size_t)gr * ldo + gc) = p;
                } else if (EPI == 1 || EPI == 3) {
                    __half2 ph = __halves2half2(__float2half_rn(x0),
                                                __float2half_rn(x1));
                    *reinterpret_cast<__half2*>(Oh + (size_t)gr * ldo + gc) = ph;
                } else {
                    fp16 h0 = __float2half_rn(x0), h1 = __float2half_rn(x1);
                    __half2 ph = __halves2half2(h0, h1);
                    __half2 pl = __halves2half2(
                        __float2half_rn(x0 - __half2float(h0)),
                        __float2half_rn(x1 - __half2float(h1)));
                    *reinterpret_cast<__half2*>(Oh + (size_t)gr * ldo + gc) = ph;
                    *reinterpret_cast<__half2*>(Ol + (size_t)gr * ldo + gc) = pl;
                }
            }
        }
}

// ---------------- kernels -----------------------------------------------------
template<int EPI, bool BTRANS, bool BSINGLE>
__global__ void __launch_bounds__(256, 2)
gemm_fp16(const fp16* __restrict__ Ap, const fp16* __restrict__ Bh,
          const fp16* __restrict__ Bl,
          fp16* __restrict__ Oh, fp16* __restrict__ Ol,
          float* __restrict__ Of,
          const float* __restrict__ bias, const void* __restrict__ mask,
          int lda, int ldb, int ldo, int K,
          long sA, long sB, long sO)
{
    extern __shared__ char smem[];
    gemm_body<EPI, BTRANS, BSINGLE>(smem, smem_u32(smem),
                                    Ap, Bh, Bl, Oh, Ol, Of, bias, mask,
                                    lda, ldb, ldo, K, sA, sB, sO,
                                    blockIdx.z, blockIdx.y * 128,
                                    blockIdx.x * 128);
}

// Fused q-proj (z==0) + v-proj (z==1); both EPI3 (bias, single-plane store).
__global__ void __launch_bounds__(256, 2)
proj_dual(const fp16* __restrict__ qin,
          const fp16* __restrict__ wqh, const fp16* __restrict__ wql,
          fp16* __restrict__ qo, const float* __restrict__ bq,
          const fp16* __restrict__ vin,
          const fp16* __restrict__ wvh, const fp16* __restrict__ wvl,
          fp16* __restrict__ vo, const float* __restrict__ bv)
{
    extern __shared__ char smem[];
    const uint32_t sm0 = smem_u32(smem);
    const int mb = blockIdx.y * 128, nb = blockIdx.x * 128;
    if (blockIdx.z == 0)
        gemm_body<3, false, false>(smem, sm0, qin, wqh, wql, qo, nullptr,
                                   nullptr, bq, nullptr,
                                   Dn, Dn, Dn, Dn, 0, 0, 0, 0, mb, nb);
    else
        gemm_body<3, false, false>(smem, sm0, vin, wvh, wvl, vo, nullptr,
                                   nullptr, bv, nullptr,
                                   Dn, Dn, Dn, Dn, 0, 0, 0, 0, mb, nb);
}

// ---------------- host side ---------------------------------------------------
extern "C" void kernel_launch(void* const* d_in, const int* in_sizes, int n_in,
                              void* d_out, int out_size)
{
    const float* queries = (const float*)d_in[0];
    const float* values  = (const float*)d_in[1];
    const void*  mask    = d_in[2];
    const float* Wq = (const float*)d_in[3];
    const float* bq = (const float*)d_in[4];
    const float* Wk = (const float*)d_in[5];
    const float* bk = (const float*)d_in[6];
    const float* Wv = (const float*)d_in[7];
    const float* bv = (const float*)d_in[8];
    float* out = (float*)d_out;

    fp16 *q, *k_h, *k_l, *v, *at, *qin, *vin;
    fp16 *wq_h, *wq_l, *wk_h, *wk_l, *wv_h, *wv_l;
    cudaGetSymbolAddress((void**)&qin, g_qin);
    cudaGetSymbolAddress((void**)&vin, g_vin);
    cudaGetSymbolAddress((void**)&wq_h, g_wq_h);
    cudaGetSymbolAddress((void**)&wq_l, g_wq_l);
    cudaGetSymbolAddress((void**)&wk_h, g_wk_h);
    cudaGetSymbolAddress((void**)&wk_l, g_wk_l);
    cudaGetSymbolAddress((void**)&wv_h, g_wv_h);
    cudaGetSymbolAddress((void**)&wv_l, g_wv_l);
    cudaGetSymbolAddress((void**)&q,   g_q);
    cudaGetSymbolAddress((void**)&k_h, g_k_h);
    cudaGetSymbolAddress((void**)&k_l, g_k_l);
    cudaGetSymbolAddress((void**)&v,   g_v);
    cudaGetSymbolAddress((void**)&at,  g_at);

    constexpr int SMEM   = 4 * 24576;            // 96 KB
    constexpr int SMEM_M = 4 * 24576 + 16384;    // 112 KB (score: +mask tile)
    static int attr_done = 0;
    if (!attr_done) {
        cudaFuncSetAttribute(proj_dual,
                             cudaFuncAttributeMaxDynamicSharedMemorySize, SMEM);
        cudaFuncSetAttribute(gemm_fp16<0, false, false>,
                             cudaFuncAttributeMaxDynamicSharedMemorySize, SMEM);
        cudaFuncSetAttribute(gemm_fp16<1, false, false>,
                             cudaFuncAttributeMaxDynamicSharedMemorySize, SMEM_M);
        cudaFuncSetAttribute(gemm_fp16<2, true, true>,
                             cudaFuncAttributeMaxDynamicSharedMemorySize, SMEM);
        attr_done = 1;
    }

    // launch 1: mask dtype detection
    detect_mask_kernel<<<1, 256>>>((const unsigned*)mask, 8192);

    // launch 2: fused prep (converts + weight splits)
    {
        const int N4 = MR * Dn / 4, W4 = Dn * Dn / 4;
        const int total = 2 * N4 + 3 * W4;
        prep_kernel<<<(total + 255) / 256, 256>>>(queries, values, Wq, Wk, Wv);
    }

    // launch 3: fused q-proj + v-proj (both single-plane outputs)
    proj_dual<<<dim3(6, 128, 2), 256, SMEM>>>(
        qin, wq_h, wq_l, q, bq, vin, wv_h, wv_l, v, bv);

    // launch 4: k = v @ Wk^T + bk -> hi/lo (B of the 2-product score GEMM)
    gemm_fp16<0, false, false><<<dim3(6, 128, 1), 256, SMEM>>>(
        v, wk_h, wk_l, k_h, k_l, nullptr, bk, nullptr,
        Dn, Dn, Dn, Dn, 0, 0, 0);

    // launch 5: score = sigmoid(mask ? q@k^T : -1e9), mask tile in smem
    gemm_fp16<1, false, false><<<dim3(16, 16, Bn), 256, SMEM_M>>>(
        q, k_h, k_l, at, nullptr, nullptr, nullptr, mask,
        Dn, Dn, LKn, Dn,
        (long)LQn * Dn, (long)LKn * Dn, (long)LQn * LKn);

    // launch 6: out = attn @ v (NN, 1-product: v single plane)
    gemm_fp16<2, true, true><<<dim3(6, 16, Bn), 256, SMEM>>>(
        at, v, v, nullptr, nullptr, out, nullptr, nullptr,
        LKn, Dn, Dn, LKn,
        (long)LQn * LKn, (long)LKn * Dn, (long)LQn * Dn);
}

// round 11
// speedup vs baseline: 2.3463x; 1.1188x over previous
#include <cuda_runtime.h>
#include <cuda_fp16.h>
#include <cstdint>
#include <cstddef>

// ============================================================================
// Problem: B=8, Lq=Lk=2048, D=768
//   q = queries@Wq^T+bq ; v = values@Wv^T+bv ; k = v@Wk^T+bk
//   attn = sigmoid(mask ? q@k^T : -1e9) ; out = attn@v
//
// Plain sm_100 target. mma.sync.m16n8k16.f32.f16.f16.f32 + ldmatrix + cp.async.
// Precision: A single fp16 plane everywhere. Projections keep W hi/lo
// (2 products). Score and context GEMMs are 1-product (k and v stored as
// single fp16 planes) -- R10 measured that B-plane quantization on long-K
// GEMMs contributes far below the per-source model (errors average down).
// R11 vs R10 (886.8us): score BSINGLE (k single plane, MACs 51.5G->25.8G),
// k-proj stores single plane. Mainloop/tiling untouched.
// ============================================================================

#define LQn 2048
#define LKn 2048
#define Dn  768
#define Bn  8
#define MR  (Bn * LQn)          // 16384

typedef __half fp16;

// ---------------- static device scratch (no cudaMalloc allowed) -------------
static __device__ fp16 g_qin[(size_t)MR * Dn];
static __device__ fp16 g_vin[(size_t)MR * Dn];
static __device__ fp16 g_wq_h[(size_t)Dn * Dn],  g_wq_l[(size_t)Dn * Dn];
static __device__ fp16 g_wk_h[(size_t)Dn * Dn],  g_wk_l[(size_t)Dn * Dn];
static __device__ fp16 g_wv_h[(size_t)Dn * Dn],  g_wv_l[(size_t)Dn * Dn];
static __device__ fp16 g_q[(size_t)MR * Dn];                       // single plane
static __device__ fp16 g_k[(size_t)MR * Dn];                       // single plane
static __device__ fp16 g_v[(size_t)MR * Dn];                       // single plane
static __device__ fp16 g_at[(size_t)Bn * LQn * LKn];               // single plane
static __device__ int  g_mask_mode;   // 0=byte, 1=int32, 2=float32

// ---------------- PTX helpers ------------------------------------------------
__device__ __forceinline__ uint32_t smem_u32(const void* p) {
    uint32_t a;
    asm("{ .reg .u64 t; cvta.to.shared.u64 t, %1; cvt.u32.u64 %0, t; }"
        : "=r"(a) : "l"(p));
    return a;
}

__device__ __forceinline__ void cpa16(uint32_t s, const void* g) {
    asm volatile("cp.async.cg.shared.global [%0], [%1], 16;"
                 :: "r"(s), "l"(g) : "memory");
}
#define CP_COMMIT() asm volatile("cp.async.commit_group;" ::: "memory")
#define CP_WAIT2()  asm volatile("cp.async.wait_group 2;"  ::: "memory")

__device__ __forceinline__ void ldsm4(uint32_t* r, uint32_t a) {
    asm volatile("ldmatrix.sync.aligned.m8n8.x4.shared.b16 {%0,%1,%2,%3}, [%4];"
                 : "=r"(r[0]), "=r"(r[1]), "=r"(r[2]), "=r"(r[3]) : "r"(a));
}
__device__ __forceinline__ void ldsm4t(uint32_t* r, uint32_t a) {
    asm volatile("ldmatrix.sync.aligned.m8n8.x4.trans.shared.b16 {%0,%1,%2,%3}, [%4];"
                 : "=r"(r[0]), "=r"(r[1]), "=r"(r[2]), "=r"(r[3]) : "r"(a));
}
__device__ __forceinline__ void mma16816(float* c, const uint32_t* a, const uint32_t* b) {
    asm volatile(
        "mma.sync.aligned.m16n8k16.row.col.f32.f16.f16.f32 "
        "{%0,%1,%2,%3}, {%4,%5,%6,%7}, {%8,%9}, {%0,%1,%2,%3};"
        : "+f"(c[0]), "+f"(c[1]), "+f"(c[2]), "+f"(c[3])
        : "r"(a[0]), "r"(a[1]), "r"(a[2]), "r"(a[3]), "r"(b[0]), "r"(b[1]));
}

__device__ __forceinline__ float sigf(float x) {
    return 1.0f / (1.0f + __expf(-x));
}

// ---------------- small kernels ----------------------------------------------
__global__ void detect_mask_kernel(const unsigned* __restrict__ w, int n) {
    int anyF = 0, anyO = 0;
    for (int i = threadIdx.x; i < n; i += blockDim.x) {
        unsigned x = w[i];
        anyF |= (x == 0x3F800000u);
        anyO |= (x != 0u && x != 1u && x != 0x3F800000u);
    }
    anyF = __syncthreads_or(anyF);
    anyO = __syncthreads_or(anyO);
    if (threadIdx.x == 0) g_mask_mode = anyF ? 2 : (anyO ? 0 : 1);
}

// Fused prep: convert queries/values -> fp16 plane; split Wq/Wk/Wv -> hi/lo.
__global__ void prep_kernel(const float* __restrict__ queries,
                            const float* __restrict__ values,
                            const float* __restrict__ Wq,
                            const float* __restrict__ Wk,
                            const float* __restrict__ Wv) {
    const int N4 = MR * Dn / 4;          // 3,145,728
    const int W4 = Dn * Dn / 4;          // 147,456
    int i = blockIdx.x * blockDim.x + threadIdx.x;

    const float* src;
    fp16 *dh, *dl = nullptr;
    int j = i;
    if (j < N4)                 { src = queries; dh = g_qin; }
    else if ((j -= N4) < N4)    { src = values;  dh = g_vin; }
    else if ((j -= N4) < W4)    { src = Wq; dh = g_wq_h; dl = g_wq_l; }
    else if ((j -= W4) < W4)    { src = Wk; dh = g_wk_h; dl = g_wk_l; }
    else if ((j -= W4) < W4)    { src = Wv; dh = g_wv_h; dl = g_wv_l; }
    else return;

    float4 x = reinterpret_cast<const float4*>(src)[j];
    fp16 h0 = __float2half_rn(x.x), h1 = __float2half_rn(x.y);
    fp16 h2 = __float2half_rn(x.z), h3 = __float2half_rn(x.w);
    reinterpret_cast<__half2*>(dh)[j * 2 + 0] = __halves2half2(h0, h1);
    reinterpret_cast<__half2*>(dh)[j * 2 + 1] = __halves2half2(h2, h3);
    if (dl) {
        __half2 l0 = __halves2half2(__float2half_rn(x.x - __half2float(h0)),
                                    __float2half_rn(x.y - __half2float(h1)));
        __half2 l1 = __halves2half2(__float2half_rn(x.z - __half2float(h2)),
                                    __float2half_rn(x.w - __half2float(h3)));
        reinterpret_cast<__half2*>(dl)[j * 2 + 0] = l0;
        reinterpret_cast<__half2*>(dl)[j * 2 + 1] = l1;
    }
}

// ---------------- GEMM body ---------------------------------------------------
// CTA tile 128x128, BK=32, 8 warps (warp tile 32x64), 4 stage buffers with
// 3 cp.async groups in flight, ONE __syncthreads per chunk, 2 CTAs/SM.
// BSINGLE=false: B hi/lo pair, acc += A*Bh + A*Bl.
// BSINGLE=true : B single plane, acc += A*Bh (half ldsm/mma/traffic).
// EPI: 0 = +bias, store fp16 hi/lo | 1 = mask+sigmoid, store fp16 single
//      | 2 = plain fp32 store | 3 = +bias, store fp16 single.
// Stage layout (24 KB): A@0  Bh@8K  Bl@16K.  EPI1: mask tile @ 96K (16 KB).
// A-type tile: 128 rows x 32 k fp16, 64 B/row: addr = r*64 + (c ^ ((r>>1)&3))*16
// B NN tile:   32 k x 128 n fp16, 256 B/row:  addr = k*256 + (ns ^ (k&7))*16

template<int EPI, bool BTRANS, bool BSINGLE>
__device__ __forceinline__ void
gemm_body(char* smem, uint32_t sm0,
          const fp16* __restrict__ Ap, const fp16* __restrict__ Bh,
          const fp16* __restrict__ Bl,
          fp16* __restrict__ Oh, fp16* __restrict__ Ol,
          float* __restrict__ Of,
          const float* __restrict__ bias, const void* __restrict__ mask,
          int lda, int ldb, int ldo, int K,
          long sA, long sB, long sO,
          int z, int mbase, int nbase)
{
    constexpr uint32_t STAGE = 24576u;
    constexpr uint32_t MASKOFF = 4u * STAGE;     // 98304

    const int tid  = threadIdx.x;

    Ap += (size_t)z * sA;
    Bh += (size_t)z * sB;
    if (!BSINGLE) Bl += (size_t)z * sB;

    const int warp = tid >> 5;
    const int lane = tid & 31;
    const int wm = warp >> 1;          // 0..3 -> rows wm*32
    const int wn = warp & 1;           // 0..1 -> cols wn*64
    const int m8 = lane >> 3;
    const int l8 = lane & 7;

    const int C = K >> 5;
    const int mode = (EPI == 1) ? g_mask_mode : 0;

    auto issue = [&](int c) {
        const int s = c & 3;
        const uint32_t sb = sm0 + (uint32_t)s * STAGE;
        const size_t ka = (size_t)c * 32;
        {
            const fp16* ga = Ap + (size_t)mbase * lda + ka;
#pragma unroll
            for (int i = 0; i < 2; ++i) {
                int seg = tid + i * 256;          // 0..511
                int r = seg >> 2, cc = seg & 3;
                uint32_t sa = sb + r * 64 + ((cc ^ ((r >> 1) & 3)) << 4);
                cpa16(sa, ga + (size_t)r * lda + cc * 8);
            }
        }
        if (!BTRANS) {
            const fp16* gh = Bh + (size_t)nbase * ldb + ka;
            const fp16* gl = BSINGLE ? nullptr : (Bl + (size_t)nbase * ldb + ka);
#pragma unroll
            for (int i = 0; i < 2; ++i) {
                int seg = tid + i * 256;
                int r = seg >> 2, cc = seg & 3;
                uint32_t sa = sb + 8192 + r * 64 + ((cc ^ ((r >> 1) & 3)) << 4);
                cpa16(sa, gh + (size_t)r * ldb + cc * 8);
                if (!BSINGLE) cpa16(sa + 8192, gl + (size_t)r * ldb + cc * 8);
            }
        } else {
            const fp16* gh = Bh + ka * ldb + nbase;
            const fp16* gl = BSINGLE ? nullptr : (Bl + ka * ldb + nbase);
#pragma unroll
            for (int i = 0; i < 2; ++i) {
                int seg = tid + i * 256;
                int k = seg >> 4, ns = seg & 15;
                uint32_t sa = sb + 8192 + k * 256 + ((ns ^ (k & 7)) << 4);
                cpa16(sa, gh + (size_t)k * ldb + ns * 8);
                if (!BSINGLE) cpa16(sa + 8192, gl + (size_t)k * ldb + ns * 8);
            }
        }
    };

    // EPI1 byte-mask: prefetch the CTA's 128x128-byte mask tile with group 0.
    if (EPI == 1 && mode == 0) {
        const unsigned char* mp = (const unsigned char*)mask
            + (size_t)z * ((size_t)LQn * LKn) + (size_t)mbase * LKn + nbase;
#pragma unroll
        for (int i = 0; i < 4; ++i) {
            int seg = tid + i * 256;              // 0..1023
            int r = seg >> 3, cc = seg & 7;       // 128 rows x 8 x16B
            cpa16(sm0 + MASKOFF + r * 128 + cc * 16,
                  mp + (size_t)r * LKn + cc * 16);
        }
    }
    issue(0); CP_COMMIT();
    issue(1); CP_COMMIT();
    issue(2); CP_COMMIT();

    float acc[2][8][4];
#pragma unroll
    for (int a = 0; a < 2; ++a)
#pragma unroll
        for (int b = 0; b < 8; ++b)
#pragma unroll
            for (int d = 0; d < 4; ++d) acc[a][b][d] = 0.0f;

    for (int c = 0; c < C; ++c) {
        CP_WAIT2();                 // stage c&3 resident
        __syncthreads();            // all warps done with stage (c-1)&3

        // refill the stage drained LAST iteration: (c+3)&3 == (c-1)&3
        if (c + 3 < C) issue(c + 3);
        CP_COMMIT();

        const uint32_t sb = sm0 + (uint32_t)(c & 3) * STAGE;

#pragma unroll
        for (int ks = 0; ks < 2; ++ks) {
            uint32_t ahf[2][4];
#pragma unroll
            for (int mt = 0; mt < 2; ++mt) {
                int r = wm * 32 + mt * 16 + (m8 & 1) * 8 + l8;
                int cA = 2 * ks + (m8 >> 1);
                uint32_t off = r * 64 + ((cA ^ ((r >> 1) & 3)) << 4);
                ldsm4(ahf[mt], sb + off);
            }
#pragma unroll
            for (int h2 = 0; h2 < 2; ++h2) {
                uint32_t bhf[2][4], blf[2][4];
#pragma unroll
                for (int gl = 0; gl < 2; ++gl) {
                    int g = h2 * 2 + gl;
                    if (!BTRANS) {
                        int n = wn * 64 + g * 16 + (m8 >> 1) * 8 + l8;
                        int cB = 2 * ks + (m8 & 1);
                        uint32_t off = n * 64 + ((cB ^ ((n >> 1) & 3)) << 4);
                        ldsm4(bhf[gl], sb + 8192 + off);
                        if (!BSINGLE) ldsm4(blf[gl], sb + 16384 + off);
                    } else {
                        int k = ks * 16 + (m8 & 1) * 8 + l8;
                        int ns = ((wn * 64 + g * 16) >> 3) + (m8 >> 1);
                        uint32_t off = k * 256 + ((ns ^ (k & 7)) << 4);
                        ldsm4t(bhf[gl], sb + 8192 + off);
                        if (!BSINGLE) ldsm4t(blf[gl], sb + 16384 + off);
                    }
                }
                // all hi products (8 independent accs), then all lo products.
#pragma unroll
                for (int mt = 0; mt < 2; ++mt)
#pragma unroll
                    for (int ntl = 0; ntl < 4; ++ntl)
                        mma16816(acc[mt][h2 * 4 + ntl], ahf[mt],
                                 &bhf[ntl >> 1][(ntl & 1) * 2]);
                if (!BSINGLE) {
#pragma unroll
                    for (int mt = 0; mt < 2; ++mt)
#pragma unroll
                        for (int ntl = 0; ntl < 4; ++ntl)
                            mma16816(acc[mt][h2 * 4 + ntl], ahf[mt],
                                     &blf[ntl >> 1][(ntl & 1) * 2]);
                }
            }
        }
    }

    // ---------------- epilogue ------------------------------------------------
    const int rb = mbase + wm * 32 + (lane >> 2);
    const int cb = nbase + wn * 64 + (lane & 3) * 2;

    if (EPI == 0) { Oh += (size_t)z * sO; Ol += (size_t)z * sO; }
    if (EPI == 1 || EPI == 3) { Oh += (size_t)z * sO; }
    if (EPI == 2) { Of += (size_t)z * sO; }

#pragma unroll
    for (int mt = 0; mt < 2; ++mt)
#pragma unroll
        for (int h = 0; h < 2; ++h) {
            const int gr = rb + mt * 16 + h * 8;
#pragma unroll
            for (int nt = 0; nt < 8; ++nt) {
                const int gc = cb + nt * 8;
                float x0 = acc[mt][nt][h * 2 + 0];
                float x1 = acc[mt][nt][h * 2 + 1];

                if (EPI == 0 || EPI == 3) {
                    x0 += bias[gc];
                    x1 += bias[gc + 1];
                } else if (EPI == 1) {
                    int f0, f1;
                    if (mode == 0) {
                        const unsigned char* ms = (const unsigned char*)smem
                            + MASKOFF + (size_t)(gr - mbase) * 128 + (gc - nbase);
                        f0 = ms[0]; f1 = ms[1];
                    } else {
                        const size_t mo = (size_t)z * ((size_t)LQn * LKn)
                                        + (size_t)gr * LKn + gc;
                        if (mode == 1) {
                            const int* mp = (const int*)mask + mo;
                            f0 = mp[0]; f1 = mp[1];
                        } else {
                            const float* mp = (const float*)mask + mo;
                            f0 = (mp[0] != 0.0f); f1 = (mp[1] != 0.0f);
                        }
                    }
                    x0 = f0 ? sigf(x0) : 0.0f;
                    x1 = f1 ? sigf(x1) : 0.0f;
                }

                if (EPI == 2) {
                    float2 p; p.x = x0; p.y = x1;
                    *reinterpret_cast<float2*>(Of + (size_t)gr * ldo + gc) = p;
                } else if (EPI == 1 || EPI == 3) {
                    __half2 ph = __halves2half2(__float2half_rn(x0),
                                                __float2half_rn(x1));
                    *reinterpret_cast<__half2*>(Oh + (size_t)gr * ldo + gc) = ph;
                } else {
                    fp16 h0 = __float2half_rn(x0), h1 = __float2half_rn(x1);
                    __half2 ph = __halves2half2(h0, h1);
                    __half2 pl = __halves2half2(
                        __float2half_rn(x0 - __half2float(h0)),
                        __float2half_rn(x1 - __half2float(h1)));
                    *reinterpret_cast<__half2*>(Oh + (size_t)gr * ldo + gc) = ph;
                    *reinterpret_cast<__half2*>(Ol + (size_t)gr * ldo + gc) = pl;
                }
            }
        }
}

// ---------------- kernels -----------------------------------------------------
template<int EPI, bool BTRANS, bool BSINGLE>
__global__ void __launch_bounds__(256, 2)
gemm_fp16(const fp16* __restrict__ Ap, const fp16* __restrict__ Bh,
          const fp16* __restrict__ Bl,
          fp16* __restrict__ Oh, fp16* __restrict__ Ol,
          float* __restrict__ Of,
          const float* __restrict__ bias, const void* __restrict__ mask,
          int lda, int ldb, int ldo, int K,
          long sA, long sB, long sO)
{
    extern __shared__ char smem[];
    gemm_body<EPI, BTRANS, BSINGLE>(smem, smem_u32(smem),
                                    Ap, Bh, Bl, Oh, Ol, Of, bias, mask,
                                    lda, ldb, ldo, K, sA, sB, sO,
                                    blockIdx.z, blockIdx.y * 128,
                                    blockIdx.x * 128);
}

// Fused q-proj (z==0) + v-proj (z==1); both EPI3 (bias, single-plane store).
__global__ void __launch_bounds__(256, 2)
proj_dual(const fp16* __restrict__ qin,
          const fp16* __restrict__ wqh, const fp16* __restrict__ wql,
          fp16* __restrict__ qo, const float* __restrict__ bq,
          const fp16* __restrict__ vin,
          const fp16* __restrict__ wvh, const fp16* __restrict__ wvl,
          fp16* __restrict__ vo, const float* __restrict__ bv)
{
    extern __shared__ char smem[];
    const uint32_t sm0 = smem_u32(smem);
    const int mb = blockIdx.y * 128, nb = blockIdx.x * 128;
    if (blockIdx.z == 0)
        gemm_body<3, false, false>(smem, sm0, qin, wqh, wql, qo, nullptr,
                                   nullptr, bq, nullptr,
                                   Dn, Dn, Dn, Dn, 0, 0, 0, 0, mb, nb);
    else
        gemm_body<3, false, false>(smem, sm0, vin, wvh, wvl, vo, nullptr,
                                   nullptr, bv, nullptr,
                                   Dn, Dn, Dn, Dn, 0, 0, 0, 0, mb, nb);
}

// ---------------- host side ---------------------------------------------------
extern "C" void kernel_launch(void* const* d_in, const int* in_sizes, int n_in,
                              void* d_out, int out_size)
{
    const float* queries = (const float*)d_in[0];
    const float* values  = (const float*)d_in[1];
    const void*  mask    = d_in[2];
    const float* Wq = (const float*)d_in[3];
    const float* bq = (const float*)d_in[4];
    const float* Wk = (const float*)d_in[5];
    const float* bk = (const float*)d_in[6];
    const float* Wv = (const float*)d_in[7];
    const float* bv = (const float*)d_in[8];
    float* out = (float*)d_out;

    fp16 *q, *k, *v, *at, *qin, *vin;
    fp16 *wq_h, *wq_l, *wk_h, *wk_l, *wv_h, *wv_l;
    cudaGetSymbolAddress((void**)&qin, g_qin);
    cudaGetSymbolAddress((void**)&vin, g_vin);
    cudaGetSymbolAddress((void**)&wq_h, g_wq_h);
    cudaGetSymbolAddress((void**)&wq_l, g_wq_l);
    cudaGetSymbolAddress((void**)&wk_h, g_wk_h);
    cudaGetSymbolAddress((void**)&wk_l, g_wk_l);
    cudaGetSymbolAddress((void**)&wv_h, g_wv_h);
    cudaGetSymbolAddress((void**)&wv_l, g_wv_l);
    cudaGetSymbolAddress((void**)&q,   g_q);
    cudaGetSymbolAddress((void**)&k,   g_k);
    cudaGetSymbolAddress((void**)&v,   g_v);
    cudaGetSymbolAddress((void**)&at,  g_at);

    constexpr int SMEM   = 4 * 24576;            // 96 KB
    constexpr int SMEM_M = 4 * 24576 + 16384;    // 112 KB (score: +mask tile)
    static int attr_done = 0;
    if (!attr_done) {
        cudaFuncSetAttribute(proj_dual,
                             cudaFuncAttributeMaxDynamicSharedMemorySize, SMEM);
        cudaFuncSetAttribute(gemm_fp16<3, false, false>,
                             cudaFuncAttributeMaxDynamicSharedMemorySize, SMEM);
        cudaFuncSetAttribute(gemm_fp16<1, false, true>,
                             cudaFuncAttributeMaxDynamicSharedMemorySize, SMEM_M);
        cudaFuncSetAttribute(gemm_fp16<2, true, true>,
                             cudaFuncAttributeMaxDynamicSharedMemorySize, SMEM);
        attr_done = 1;
    }

    // launch 1: mask dtype detection
    detect_mask_kernel<<<1, 256>>>((const unsigned*)mask, 8192);

    // launch 2: fused prep (converts + weight splits)
    {
        const int N4 = MR * Dn / 4, W4 = Dn * Dn / 4;
        const int total = 2 * N4 + 3 * W4;
        prep_kernel<<<(total + 255) / 256, 256>>>(queries, values, Wq, Wk, Wv);
    }

    // launch 3: fused q-proj + v-proj (both single-plane outputs, 2-product)
    proj_dual<<<dim3(6, 128, 2), 256, SMEM>>>(
        qin, wq_h, wq_l, q, bq, vin, wv_h, wv_l, v, bv);

    // launch 4: k = v @ Wk^T + bk -> single plane (2-product over Wk hi/lo)
    gemm_fp16<3, false, false><<<dim3(6, 128, 1), 256, SMEM>>>(
        v, wk_h, wk_l, k, nullptr, nullptr, bk, nullptr,
        Dn, Dn, Dn, Dn, 0, 0, 0);

    // launch 5: score = sigmoid(mask ? q@k^T : -1e9), 1-product (k single),
    //           mask tile prefetched to smem
    gemm_fp16<1, false, true><<<dim3(16, 16, Bn), 256, SMEM_M>>>(
        q, k, k, at, nullptr, nullptr, nullptr, mask,
        Dn, Dn, LKn, Dn,
        (long)LQn * Dn, (long)LKn * Dn, (long)LQn * LKn);

    // launch 6: out = attn @ v (NN, 1-product: v single plane)
    gemm_fp16<2, true, true><<<dim3(6, 16, Bn), 256, SMEM>>>(
        at, v, v, nullptr, nullptr, out, nullptr, nullptr,
        LKn, Dn, Dn, LKn,
        (long)LQn * LKn, (long)LKn * Dn, (long)LQn * Dn);
}

// round 12
// speedup vs baseline: 2.7920x; 1.1900x over previous
#include <cuda_runtime.h>
#include <cuda_fp16.h>
#include <cstdint>
#include <cstddef>

// ============================================================================
// Problem: B=8, Lq=Lk=2048, D=768
//   q = queries@Wq^T+bq ; v = values@Wv^T+bv ; k = v@Wk^T+bk
//   attn = sigmoid(mask ? q@k^T : -1e9) ; out = attn@v
//
// Plain sm_100 target. mma.sync.m16n8k16.f32.f16.f16.f32 + ldmatrix + cp.async.
// R12: PURE fp16 single-plane everywhere (all 5 GEMMs 1-product, 80.6G MACs —
// the ISA minimum). Error budget built from measured per-source contributions
// (R10: v-drop +1.31e-4, R11: k-drop +2.57e-4 in quadrature): predicted
// ~7.2e-4 < 1e-3, deterministic inputs.
// Mainloop/tiling untouched (tensor=58.5% measured; structural limit at
// 2 CTA/SM, 128 regs).
// ============================================================================

#define LQn 2048
#define LKn 2048
#define Dn  768
#define Bn  8
#define MR  (Bn * LQn)          // 16384

typedef __half fp16;

// ---------------- static device scratch (no cudaMalloc allowed) -------------
static __device__ fp16 g_qin[(size_t)MR * Dn];
static __device__ fp16 g_vin[(size_t)MR * Dn];
static __device__ fp16 g_wq[(size_t)Dn * Dn];
static __device__ fp16 g_wk[(size_t)Dn * Dn];
static __device__ fp16 g_wv[(size_t)Dn * Dn];
static __device__ fp16 g_q[(size_t)MR * Dn];
static __device__ fp16 g_k[(size_t)MR * Dn];
static __device__ fp16 g_v[(size_t)MR * Dn];
static __device__ fp16 g_at[(size_t)Bn * LQn * LKn];
static __device__ int  g_mask_mode;   // 0=byte, 1=int32, 2=float32

// ---------------- PTX helpers ------------------------------------------------
__device__ __forceinline__ uint32_t smem_u32(const void* p) {
    uint32_t a;
    asm("{ .reg .u64 t; cvta.to.shared.u64 t, %1; cvt.u32.u64 %0, t; }"
        : "=r"(a) : "l"(p));
    return a;
}

__device__ __forceinline__ void cpa16(uint32_t s, const void* g) {
    asm volatile("cp.async.cg.shared.global [%0], [%1], 16;"
                 :: "r"(s), "l"(g) : "memory");
}
#define CP_COMMIT() asm volatile("cp.async.commit_group;" ::: "memory")
#define CP_WAIT2()  asm volatile("cp.async.wait_group 2;"  ::: "memory")

__device__ __forceinline__ void ldsm4(uint32_t* r, uint32_t a) {
    asm volatile("ldmatrix.sync.aligned.m8n8.x4.shared.b16 {%0,%1,%2,%3}, [%4];"
                 : "=r"(r[0]), "=r"(r[1]), "=r"(r[2]), "=r"(r[3]) : "r"(a));
}
__device__ __forceinline__ void ldsm4t(uint32_t* r, uint32_t a) {
    asm volatile("ldmatrix.sync.aligned.m8n8.x4.trans.shared.b16 {%0,%1,%2,%3}, [%4];"
                 : "=r"(r[0]), "=r"(r[1]), "=r"(r[2]), "=r"(r[3]) : "r"(a));
}
__device__ __forceinline__ void mma16816(float* c, const uint32_t* a, const uint32_t* b) {
    asm volatile(
        "mma.sync.aligned.m16n8k16.row.col.f32.f16.f16.f32 "
        "{%0,%1,%2,%3}, {%4,%5,%6,%7}, {%8,%9}, {%0,%1,%2,%3};"
        : "+f"(c[0]), "+f"(c[1]), "+f"(c[2]), "+f"(c[3])
        : "r"(a[0]), "r"(a[1]), "r"(a[2]), "r"(a[3]), "r"(b[0]), "r"(b[1]));
}

__device__ __forceinline__ float sigf(float x) {
    return 1.0f / (1.0f + __expf(-x));
}

// ---------------- small kernels ----------------------------------------------
__global__ void detect_mask_kernel(const unsigned* __restrict__ w, int n) {
    int anyF = 0, anyO = 0;
    for (int i = threadIdx.x; i < n; i += blockDim.x) {
        unsigned x = w[i];
        anyF |= (x == 0x3F800000u);
        anyO |= (x != 0u && x != 1u && x != 0x3F800000u);
    }
    anyF = __syncthreads_or(anyF);
    anyO = __syncthreads_or(anyO);
    if (threadIdx.x == 0) g_mask_mode = anyF ? 2 : (anyO ? 0 : 1);
}

// Fused prep: convert all five fp32 inputs to single fp16 planes.
__global__ void prep_kernel(const float* __restrict__ queries,
                            const float* __restrict__ values,
                            const float* __restrict__ Wq,
                            const float* __restrict__ Wk,
                            const float* __restrict__ Wv) {
    const int N4 = MR * Dn / 4;          // 3,145,728
    const int W4 = Dn * Dn / 4;          // 147,456
    int i = blockIdx.x * blockDim.x + threadIdx.x;

    const float* src;
    fp16* dh;
    int j = i;
    if (j < N4)                 { src = queries; dh = g_qin; }
    else if ((j -= N4) < N4)    { src = values;  dh = g_vin; }
    else if ((j -= N4) < W4)    { src = Wq; dh = g_wq; }
    else if ((j -= W4) < W4)    { src = Wk; dh = g_wk; }
    else if ((j -= W4) < W4)    { src = Wv; dh = g_wv; }
    else return;

    float4 x = reinterpret_cast<const float4*>(src)[j];
    reinterpret_cast<__half2*>(dh)[j * 2 + 0] =
        __halves2half2(__float2half_rn(x.x), __float2half_rn(x.y));
    reinterpret_cast<__half2*>(dh)[j * 2 + 1] =
        __halves2half2(__float2half_rn(x.z), __float2half_rn(x.w));
}

// ---------------- GEMM body ---------------------------------------------------
// CTA tile 128x128, BK=32, 8 warps (warp tile 32x64), 4 stage buffers with
// 3 cp.async groups in flight, ONE __syncthreads per chunk, 2 CTAs/SM.
// Pure fp16 1-product: acc += A*B.
// EPI: 1 = mask+sigmoid, store fp16 | 2 = plain fp32 store | 3 = +bias, fp16.
// Stage layout (16 KB): A@0  B@8K.  EPI1: mask tile @ 64K (16 KB).
// A-type tile: 128 rows x 32 k fp16, 64 B/row: addr = r*64 + (c ^ ((r>>1)&3))*16
// B NN tile:   32 k x 128 n fp16, 256 B/row:  addr = k*256 + (ns ^ (k&7))*16

template<int EPI, bool BTRANS>
__device__ __forceinline__ void
gemm_body(char* smem, uint32_t sm0,
          const fp16* __restrict__ Ap, const fp16* __restrict__ Bp,
          fp16* __restrict__ Oh, float* __restrict__ Of,
          const float* __restrict__ bias, const void* __restrict__ mask,
          int lda, int ldb, int ldo, int K,
          long sA, long sB, long sO,
          int z, int mbase, int nbase)
{
    constexpr uint32_t STAGE = 16384u;
    constexpr uint32_t MASKOFF = 4u * STAGE;     // 65536

    const int tid  = threadIdx.x;

    Ap += (size_t)z * sA;
    Bp += (size_t)z * sB;

    const int warp = tid >> 5;
    const int lane = tid & 31;
    const int wm = warp >> 1;          // 0..3 -> rows wm*32
    const int wn = warp & 1;           // 0..1 -> cols wn*64
    const int m8 = lane >> 3;
    const int l8 = lane & 7;

    const int C = K >> 5;
    const int mode = (EPI == 1) ? g_mask_mode : 0;

    auto issue = [&](int c) {
        const int s = c & 3;
        const uint32_t sb = sm0 + (uint32_t)s * STAGE;
        const size_t ka = (size_t)c * 32;
        {
            const fp16* ga = Ap + (size_t)mbase * lda + ka;
#pragma unroll
            for (int i = 0; i < 2; ++i) {
                int seg = tid + i * 256;          // 0..511
                int r = seg >> 2, cc = seg & 3;
                uint32_t sa = sb + r * 64 + ((cc ^ ((r >> 1) & 3)) << 4);
                cpa16(sa, ga + (size_t)r * lda + cc * 8);
            }
        }
        if (!BTRANS) {
            const fp16* gb = Bp + (size_t)nbase * ldb + ka;
#pragma unroll
            for (int i = 0; i < 2; ++i) {
                int seg = tid + i * 256;
                int r = seg >> 2, cc = seg & 3;
                uint32_t sa = sb + 8192 + r * 64 + ((cc ^ ((r >> 1) & 3)) << 4);
                cpa16(sa, gb + (size_t)r * ldb + cc * 8);
            }
        } else {
            const fp16* gb = Bp + ka * ldb + nbase;
#pragma unroll
            for (int i = 0; i < 2; ++i) {
                int seg = tid + i * 256;
                int k = seg >> 4, ns = seg & 15;
                uint32_t sa = sb + 8192 + k * 256 + ((ns ^ (k & 7)) << 4);
                cpa16(sa, gb + (size_t)k * ldb + ns * 8);
            }
        }
    };

    // EPI1 byte-mask: prefetch the CTA's 128x128-byte mask tile with group 0.
    if (EPI == 1 && mode == 0) {
        const unsigned char* mp = (const unsigned char*)mask
            + (size_t)z * ((size_t)LQn * LKn) + (size_t)mbase * LKn + nbase;
#pragma unroll
        for (int i = 0; i < 4; ++i) {
            int seg = tid + i * 256;              // 0..1023
            int r = seg >> 3, cc = seg & 7;       // 128 rows x 8 x16B
            cpa16(sm0 + MASKOFF + r * 128 + cc * 16,
                  mp + (size_t)r * LKn + cc * 16);
        }
    }
    issue(0); CP_COMMIT();
    issue(1); CP_COMMIT();
    issue(2); CP_COMMIT();

    float acc[2][8][4];
#pragma unroll
    for (int a = 0; a < 2; ++a)
#pragma unroll
        for (int b = 0; b < 8; ++b)
#pragma unroll
            for (int d = 0; d < 4; ++d) acc[a][b][d] = 0.0f;

    for (int c = 0; c < C; ++c) {
        CP_WAIT2();                 // stage c&3 resident
        __syncthreads();            // all warps done with stage (c-1)&3

        // refill the stage drained LAST iteration: (c+3)&3 == (c-1)&3
        if (c + 3 < C) issue(c + 3);
        CP_COMMIT();

        const uint32_t sb = sm0 + (uint32_t)(c & 3) * STAGE;

#pragma unroll
        for (int ks = 0; ks < 2; ++ks) {
            uint32_t ahf[2][4];
#pragma unroll
            for (int mt = 0; mt < 2; ++mt) {
                int r = wm * 32 + mt * 16 + (m8 & 1) * 8 + l8;
                int cA = 2 * ks + (m8 >> 1);
                uint32_t off = r * 64 + ((cA ^ ((r >> 1) & 3)) << 4);
                ldsm4(ahf[mt], sb + off);
            }
#pragma unroll
            for (int h2 = 0; h2 < 2; ++h2) {
                uint32_t bhf[2][4];
#pragma unroll
                for (int gl = 0; gl < 2; ++gl) {
                    int g = h2 * 2 + gl;
                    if (!BTRANS) {
                        int n = wn * 64 + g * 16 + (m8 >> 1) * 8 + l8;
                        int cB = 2 * ks + (m8 & 1);
                        uint32_t off = n * 64 + ((cB ^ ((n >> 1) & 3)) << 4);
                        ldsm4(bhf[gl], sb + 8192 + off);
                    } else {
                        int k = ks * 16 + (m8 & 1) * 8 + l8;
                        int ns = ((wn * 64 + g * 16) >> 3) + (m8 >> 1);
                        uint32_t off = k * 256 + ((ns ^ (k & 7)) << 4);
                        ldsm4t(bhf[gl], sb + 8192 + off);
                    }
                }
#pragma unroll
                for (int mt = 0; mt < 2; ++mt)
#pragma unroll
                    for (int ntl = 0; ntl < 4; ++ntl)
                        mma16816(acc[mt][h2 * 4 + ntl], ahf[mt],
                                 &bhf[ntl >> 1][(ntl & 1) * 2]);
            }
        }
    }

    // ---------------- epilogue ------------------------------------------------
    const int rb = mbase + wm * 32 + (lane >> 2);
    const int cb = nbase + wn * 64 + (lane & 3) * 2;

    if (EPI == 1 || EPI == 3) { Oh += (size_t)z * sO; }
    if (EPI == 2) { Of += (size_t)z * sO; }

#pragma unroll
    for (int mt = 0; mt < 2; ++mt)
#pragma unroll
        for (int h = 0; h < 2; ++h) {
            const int gr = rb + mt * 16 + h * 8;
#pragma unroll
            for (int nt = 0; nt < 8; ++nt) {
                const int gc = cb + nt * 8;
                float x0 = acc[mt][nt][h * 2 + 0];
                float x1 = acc[mt][nt][h * 2 + 1];

                if (EPI == 3) {
                    x0 += bias[gc];
                    x1 += bias[gc + 1];
                } else if (EPI == 1) {
                    int f0, f1;
                    if (mode == 0) {
                        const unsigned char* ms = (const unsigned char*)smem
                            + MASKOFF + (size_t)(gr - mbase) * 128 + (gc - nbase);
                        f0 = ms[0]; f1 = ms[1];
                    } else {
                        const size_t mo = (size_t)z * ((size_t)LQn * LKn)
                                        + (size_t)gr * LKn + gc;
                        if (mode == 1) {
                            const int* mp = (const int*)mask + mo;
                            f0 = mp[0]; f1 = mp[1];
                        } else {
                            const float* mp = (const float*)mask + mo;
                            f0 = (mp[0] != 0.0f); f1 = (mp[1] != 0.0f);
                        }
                    }
                    x0 = f0 ? sigf(x0) : 0.0f;
                    x1 = f1 ? sigf(x1) : 0.0f;
                }

                if (EPI == 2) {
                    float2 p; p.x = x0; p.y = x1;
                    *reinterpret_cast<float2*>(Of + (size_t)gr * ldo + gc) = p;
                } else {
                    __half2 ph = __halves2half2(__float2half_rn(x0),
                                                __float2half_rn(x1));
                    *reinterpret_cast<__half2*>(Oh + (size_t)gr * ldo + gc) = ph;
                }
            }
        }
}

// ---------------- kernels -----------------------------------------------------
template<int EPI, bool BTRANS>
__global__ void __launch_bounds__(256, 2)
gemm_fp16(const fp16* __restrict__ Ap, const fp16* __restrict__ Bp,
          fp16* __restrict__ Oh, float* __restrict__ Of,
          const float* __restrict__ bias, const void* __restrict__ mask,
          int lda, int ldb, int ldo, int K,
          long sA, long sB, long sO)
{
    extern __shared__ char smem[];
    gemm_body<EPI, BTRANS>(smem, smem_u32(smem),
                           Ap, Bp, Oh, Of, bias, mask,
                           lda, ldb, ldo, K, sA, sB, sO,
                           blockIdx.z, blockIdx.y * 128, blockIdx.x * 128);
}

// Fused q-proj (z==0) + v-proj (z==1); both EPI3 (bias, fp16 store).
__global__ void __launch_bounds__(256, 2)
proj_dual(const fp16* __restrict__ qin, const fp16* __restrict__ wq,
          fp16* __restrict__ qo, const float* __restrict__ bq,
          const fp16* __restrict__ vin, const fp16* __restrict__ wv,
          fp16* __restrict__ vo, const float* __restrict__ bv)
{
    extern __shared__ char smem[];
    const uint32_t sm0 = smem_u32(smem);
    const int mb = blockIdx.y * 128, nb = blockIdx.x * 128;
    if (blockIdx.z == 0)
        gemm_body<3, false>(smem, sm0, qin, wq, qo, nullptr, bq, nullptr,
                            Dn, Dn, Dn, Dn, 0, 0, 0, 0, mb, nb);
    else
        gemm_body<3, false>(smem, sm0, vin, wv, vo, nullptr, bv, nullptr,
                            Dn, Dn, Dn, Dn, 0, 0, 0, 0, mb, nb);
}

// ---------------- host side ---------------------------------------------------
extern "C" void kernel_launch(void* const* d_in, const int* in_sizes, int n_in,
                              void* d_out, int out_size)
{
    const float* queries = (const float*)d_in[0];
    const float* values  = (const float*)d_in[1];
    const void*  mask    = d_in[2];
    const float* Wq = (const float*)d_in[3];
    const float* bq = (const float*)d_in[4];
    const float* Wk = (const float*)d_in[5];
    const float* bk = (const float*)d_in[6];
    const float* Wv = (const float*)d_in[7];
    const float* bv = (const float*)d_in[8];
    float* out = (float*)d_out;

    fp16 *q, *k, *v, *at, *qin, *vin, *wq, *wk, *wv;
    cudaGetSymbolAddress((void**)&qin, g_qin);
    cudaGetSymbolAddress((void**)&vin, g_vin);
    cudaGetSymbolAddress((void**)&wq,  g_wq);
    cudaGetSymbolAddress((void**)&wk,  g_wk);
    cudaGetSymbolAddress((void**)&wv,  g_wv);
    cudaGetSymbolAddress((void**)&q,   g_q);
    cudaGetSymbolAddress((void**)&k,   g_k);
    cudaGetSymbolAddress((void**)&v,   g_v);
    cudaGetSymbolAddress((void**)&at,  g_at);

    constexpr int SMEM   = 4 * 16384;            // 64 KB
    constexpr int SMEM_M = 4 * 16384 + 16384;    // 80 KB (score: +mask tile)
    static int attr_done = 0;
    if (!attr_done) {
        cudaFuncSetAttribute(proj_dual,
                             cudaFuncAttributeMaxDynamicSharedMemorySize, SMEM);
        cudaFuncSetAttribute(gemm_fp16<3, false>,
                             cudaFuncAttributeMaxDynamicSharedMemorySize, SMEM);
        cudaFuncSetAttribute(gemm_fp16<1, false>,
                             cudaFuncAttributeMaxDynamicSharedMemorySize, SMEM_M);
        cudaFuncSetAttribute(gemm_fp16<2, true>,
                             cudaFuncAttributeMaxDynamicSharedMemorySize, SMEM);
        attr_done = 1;
    }

    // launch 1: mask dtype detection
    detect_mask_kernel<<<1, 256>>>((const unsigned*)mask, 8192);

    // launch 2: fused prep (pure fp16 converts)
    {
        const int N4 = MR * Dn / 4, W4 = Dn * Dn / 4;
        const int total = 2 * N4 + 3 * W4;
        prep_kernel<<<(total + 255) / 256, 256>>>(queries, values, Wq, Wk, Wv);
    }

    // launch 3: fused q-proj + v-proj
    proj_dual<<<dim3(6, 128, 2), 256, SMEM>>>(
        qin, wq, q, bq, vin, wv, v, bv);

    // launch 4: k = v @ Wk^T + bk
    gemm_fp16<3, false><<<dim3(6, 128, 1), 256, SMEM>>>(
        v, wk, k, nullptr, bk, nullptr,
        Dn, Dn, Dn, Dn, 0, 0, 0);

    // launch 5: score = sigmoid(mask ? q@k^T : -1e9), mask tile in smem
    gemm_fp16<1, false><<<dim3(16, 16, Bn), 256, SMEM_M>>>(
        q, k, at, nullptr, nullptr, mask,
        Dn, Dn, LKn, Dn,
        (long)LQn * Dn, (long)LKn * Dn, (long)LQn * LKn);

    // launch 6: out = attn @ v (NN)
    gemm_fp16<2, true><<<dim3(6, 16, Bn), 256, SMEM>>>(
        at, v, nullptr, out, nullptr, nullptr,
        LKn, Dn, Dn, LKn,
        (long)LQn * LKn, (long)LKn * Dn, (long)LQn * Dn);
}

// round 13
// speedup vs baseline: 3.0269x; 1.0841x over previous
#include <cuda_runtime.h>
#include <cuda_fp16.h>
#include <cstdint>
#include <cstddef>

// ============================================================================
// Problem: B=8, Lq=Lk=2048, D=768
//   q = queries@Wq^T+bq ; v = values@Wv^T+bv ; k = v@Wk^T+bk
//   attn = sigmoid(mask ? q@k^T : -1e9) ; out = attn@v
//
// Plain sm_100 target. mma.sync.m16n8k16.f32.f16.f16.f32 + ldmatrix + cp.async.
// Pure fp16 single-plane everywhere (ISA-minimum 80.6G MACs; measured
// rel_err 8.06e-4 at BK=32 -- arithmetic here is bit-identical).
// R13 vs R12 (666us): BK 32->64, 3-stage pipeline (32 KB/stage). Halves
// per-chunk barriers and doubles mma burst length to amortize the
// sync/ldsm-rampup overhead that left tensor at 48%.
// ============================================================================

#define LQn 2048
#define LKn 2048
#define Dn  768
#define Bn  8
#define MR  (Bn * LQn)          // 16384

typedef __half fp16;

// ---------------- static device scratch (no cudaMalloc allowed) -------------
static __device__ fp16 g_qin[(size_t)MR * Dn];
static __device__ fp16 g_vin[(size_t)MR * Dn];
static __device__ fp16 g_wq[(size_t)Dn * Dn];
static __device__ fp16 g_wk[(size_t)Dn * Dn];
static __device__ fp16 g_wv[(size_t)Dn * Dn];
static __device__ fp16 g_q[(size_t)MR * Dn];
static __device__ fp16 g_k[(size_t)MR * Dn];
static __device__ fp16 g_v[(size_t)MR * Dn];
static __device__ fp16 g_at[(size_t)Bn * LQn * LKn];
static __device__ int  g_mask_mode;   // 0=byte, 1=int32, 2=float32

// ---------------- PTX helpers ------------------------------------------------
__device__ __forceinline__ uint32_t smem_u32(const void* p) {
    uint32_t a;
    asm("{ .reg .u64 t; cvta.to.shared.u64 t, %1; cvt.u32.u64 %0, t; }"
        : "=r"(a) : "l"(p));
    return a;
}

__device__ __forceinline__ void cpa16(uint32_t s, const void* g) {
    asm volatile("cp.async.cg.shared.global [%0], [%1], 16;"
                 :: "r"(s), "l"(g) : "memory");
}
#define CP_COMMIT() asm volatile("cp.async.commit_group;" ::: "memory")
#define CP_WAIT1()  asm volatile("cp.async.wait_group 1;"  ::: "memory")

__device__ __forceinline__ void ldsm4(uint32_t* r, uint32_t a) {
    asm volatile("ldmatrix.sync.aligned.m8n8.x4.shared.b16 {%0,%1,%2,%3}, [%4];"
                 : "=r"(r[0]), "=r"(r[1]), "=r"(r[2]), "=r"(r[3]) : "r"(a));
}
__device__ __forceinline__ void ldsm4t(uint32_t* r, uint32_t a) {
    asm volatile("ldmatrix.sync.aligned.m8n8.x4.trans.shared.b16 {%0,%1,%2,%3}, [%4];"
                 : "=r"(r[0]), "=r"(r[1]), "=r"(r[2]), "=r"(r[3]) : "r"(a));
}
__device__ __forceinline__ void mma16816(float* c, const uint32_t* a, const uint32_t* b) {
    asm volatile(
        "mma.sync.aligned.m16n8k16.row.col.f32.f16.f16.f32 "
        "{%0,%1,%2,%3}, {%4,%5,%6,%7}, {%8,%9}, {%0,%1,%2,%3};"
        : "+f"(c[0]), "+f"(c[1]), "+f"(c[2]), "+f"(c[3])
        : "r"(a[0]), "r"(a[1]), "r"(a[2]), "r"(a[3]), "r"(b[0]), "r"(b[1]));
}

__device__ __forceinline__ float sigf(float x) {
    return 1.0f / (1.0f + __expf(-x));
}

// ---------------- small kernels ----------------------------------------------
__global__ void detect_mask_kernel(const unsigned* __restrict__ w, int n) {
    int anyF = 0, anyO = 0;
    for (int i = threadIdx.x; i < n; i += blockDim.x) {
        unsigned x = w[i];
        anyF |= (x == 0x3F800000u);
        anyO |= (x != 0u && x != 1u && x != 0x3F800000u);
    }
    anyF = __syncthreads_or(anyF);
    anyO = __syncthreads_or(anyO);
    if (threadIdx.x == 0) g_mask_mode = anyF ? 2 : (anyO ? 0 : 1);
}

// Fused prep: convert all five fp32 inputs to single fp16 planes.
__global__ void prep_kernel(const float* __restrict__ queries,
                            const float* __restrict__ values,
                            const float* __restrict__ Wq,
                            const float* __restrict__ Wk,
                            const float* __restrict__ Wv) {
    const int N4 = MR * Dn / 4;          // 3,145,728
    const int W4 = Dn * Dn / 4;          // 147,456
    int i = blockIdx.x * blockDim.x + threadIdx.x;

    const float* src;
    fp16* dh;
    int j = i;
    if (j < N4)                 { src = queries; dh = g_qin; }
    else if ((j -= N4) < N4)    { src = values;  dh = g_vin; }
    else if ((j -= N4) < W4)    { src = Wq; dh = g_wq; }
    else if ((j -= W4) < W4)    { src = Wk; dh = g_wk; }
    else if ((j -= W4) < W4)    { src = Wv; dh = g_wv; }
    else return;

    float4 x = reinterpret_cast<const float4*>(src)[j];
    reinterpret_cast<__half2*>(dh)[j * 2 + 0] =
        __halves2half2(__float2half_rn(x.x), __float2half_rn(x.y));
    reinterpret_cast<__half2*>(dh)[j * 2 + 1] =
        __halves2half2(__float2half_rn(x.z), __float2half_rn(x.w));
}

// ---------------- GEMM body ---------------------------------------------------
// CTA tile 128x128, BK=64, 8 warps (warp tile 32x64), 3 stage buffers with
// 2 cp.async groups in flight, ONE __syncthreads per chunk, 2 CTAs/SM.
// Pure fp16 1-product: acc += A*B.
// EPI: 1 = mask+sigmoid, store fp16 | 2 = plain fp32 store | 3 = +bias, fp16.
// Stage layout (32 KB): A@0  B@16K.  EPI1: mask tile @ 96K (16 KB).
// A / B-NT tile: 128 rows x 64 k fp16, 128 B/row:
//   addr = r*128 + ((c ^ (r&7)) << 4), c in 0..7
// B NN tile: 64 k x 128 n fp16, 256 B/row:
//   addr = k*256 + ((ns ^ (k&7)) << 4), ns in 0..15

template<int EPI, bool BTRANS>
__device__ __forceinline__ void
gemm_body(char* smem, uint32_t sm0,
          const fp16* __restrict__ Ap, const fp16* __restrict__ Bp,
          fp16* __restrict__ Oh, float* __restrict__ Of,
          const float* __restrict__ bias, const void* __restrict__ mask,
          int lda, int ldb, int ldo, int K,
          long sA, long sB, long sO,
          int z, int mbase, int nbase)
{
    constexpr uint32_t STAGE = 32768u;
    constexpr uint32_t MASKOFF = 3u * STAGE;     // 98304

    const int tid  = threadIdx.x;

    Ap += (size_t)z * sA;
    Bp += (size_t)z * sB;

    const int warp = tid >> 5;
    const int lane = tid & 31;
    const int wm = warp >> 1;          // 0..3 -> rows wm*32
    const int wn = warp & 1;           // 0..1 -> cols wn*64
    const int m8 = lane >> 3;
    const int l8 = lane & 7;

    const int C = K >> 6;              // chunks of 64
    const int mode = (EPI == 1) ? g_mask_mode : 0;

    auto issue = [&](int c) {
        // s = c % 3 (C <= 32, cheap)
        const int s = c - (c / 3) * 3;
        const uint32_t sb = sm0 + (uint32_t)s * STAGE;
        const size_t ka = (size_t)c * 64;
        {
            // A tile: 1024 segs of 16 B; 256 threads x 4
            const fp16* ga = Ap + (size_t)mbase * lda + ka;
#pragma unroll
            for (int i = 0; i < 4; ++i) {
                int seg = tid + i * 256;          // 0..1023
                int r = seg >> 3, cc = seg & 7;
                uint32_t sa = sb + r * 128 + ((cc ^ (r & 7)) << 4);
                cpa16(sa, ga + (size_t)r * lda + cc * 8);
            }
        }
        if (!BTRANS) {
            const fp16* gb = Bp + (size_t)nbase * ldb + ka;
#pragma unroll
            for (int i = 0; i < 4; ++i) {
                int seg = tid + i * 256;
                int r = seg >> 3, cc = seg & 7;
                uint32_t sa = sb + 16384 + r * 128 + ((cc ^ (r & 7)) << 4);
                cpa16(sa, gb + (size_t)r * ldb + cc * 8);
            }
        } else {
            // 64 k-rows x 16 n-segs
            const fp16* gb = Bp + ka * ldb + nbase;
#pragma unroll
            for (int i = 0; i < 4; ++i) {
                int seg = tid + i * 256;
                int k = seg >> 4, ns = seg & 15;
                uint32_t sa = sb + 16384 + k * 256 + ((ns ^ (k & 7)) << 4);
                cpa16(sa, gb + (size_t)k * ldb + ns * 8);
            }
        }
    };

    // EPI1 byte-mask: prefetch the CTA's 128x128-byte mask tile with group 0.
    if (EPI == 1 && mode == 0) {
        const unsigned char* mp = (const unsigned char*)mask
            + (size_t)z * ((size_t)LQn * LKn) + (size_t)mbase * LKn + nbase;
#pragma unroll
        for (int i = 0; i < 4; ++i) {
            int seg = tid + i * 256;              // 0..1023
            int r = seg >> 3, cc = seg & 7;       // 128 rows x 8 x16B
            cpa16(sm0 + MASKOFF + r * 128 + cc * 16,
                  mp + (size_t)r * LKn + cc * 16);
        }
    }
    issue(0); CP_COMMIT();
    issue(1); CP_COMMIT();

    float acc[2][8][4];
#pragma unroll
    for (int a = 0; a < 2; ++a)
#pragma unroll
        for (int b = 0; b < 8; ++b)
#pragma unroll
            for (int d = 0; d < 4; ++d) acc[a][b][d] = 0.0f;

    for (int c = 0; c < C; ++c) {
        CP_WAIT1();                 // stage c%3 resident (<=1 group pending)
        __syncthreads();            // all warps done with stage (c-1)%3

        // refill the stage drained LAST iteration: (c+2)%3 == (c-1)%3
        if (c + 2 < C) issue(c + 2);
        CP_COMMIT();

        const int s = c - (c / 3) * 3;
        const uint32_t sb = sm0 + (uint32_t)s * STAGE;

#pragma unroll
        for (int ks = 0; ks < 4; ++ks) {
            uint32_t ahf[2][4];
#pragma unroll
            for (int mt = 0; mt < 2; ++mt) {
                int r = wm * 32 + mt * 16 + (m8 & 1) * 8 + l8;
                int cA = 2 * ks + (m8 >> 1);
                uint32_t off = r * 128 + ((cA ^ (r & 7)) << 4);
                ldsm4(ahf[mt], sb + off);
            }
#pragma unroll
            for (int h2 = 0; h2 < 2; ++h2) {
                uint32_t bhf[2][4];
#pragma unroll
                for (int gl = 0; gl < 2; ++gl) {
                    int g = h2 * 2 + gl;
                    if (!BTRANS) {
                        int n = wn * 64 + g * 16 + (m8 >> 1) * 8 + l8;
                        int cB = 2 * ks + (m8 & 1);
                        uint32_t off = n * 128 + ((cB ^ (n & 7)) << 4);
                        ldsm4(bhf[gl], sb + 16384 + off);
                    } else {
                        int k = ks * 16 + (m8 & 1) * 8 + l8;
                        int ns = ((wn * 64 + g * 16) >> 3) + (m8 >> 1);
                        uint32_t off = k * 256 + ((ns ^ (k & 7)) << 4);
                        ldsm4t(bhf[gl], sb + 16384 + off);
                    }
                }
#pragma unroll
                for (int mt = 0; mt < 2; ++mt)
#pragma unroll
                    for (int ntl = 0; ntl < 4; ++ntl)
                        mma16816(acc[mt][h2 * 4 + ntl], ahf[mt],
                                 &bhf[ntl >> 1][(ntl & 1) * 2]);
            }
        }
    }

    // ---------------- epilogue ------------------------------------------------
    const int rb = mbase + wm * 32 + (lane >> 2);
    const int cb = nbase + wn * 64 + (lane & 3) * 2;

    if (EPI == 1 || EPI == 3) { Oh += (size_t)z * sO; }
    if (EPI == 2) { Of += (size_t)z * sO; }

#pragma unroll
    for (int mt = 0; mt < 2; ++mt)
#pragma unroll
        for (int h = 0; h < 2; ++h) {
            const int gr = rb + mt * 16 + h * 8;
#pragma unroll
            for (int nt = 0; nt < 8; ++nt) {
                const int gc = cb + nt * 8;
                float x0 = acc[mt][nt][h * 2 + 0];
                float x1 = acc[mt][nt][h * 2 + 1];

                if (EPI == 3) {
                    x0 += bias[gc];
                    x1 += bias[gc + 1];
                } else if (EPI == 1) {
                    int f0, f1;
                    if (mode == 0) {
                        const unsigned char* ms = (const unsigned char*)smem
                            + MASKOFF + (size_t)(gr - mbase) * 128 + (gc - nbase);
                        f0 = ms[0]; f1 = ms[1];
                    } else {
                        const size_t mo = (size_t)z * ((size_t)LQn * LKn)
                                        + (size_t)gr * LKn + gc;
                        if (mode == 1) {
                            const int* mp = (const int*)mask + mo;
                            f0 = mp[0]; f1 = mp[1];
                        } else {
                            const float* mp = (const float*)mask + mo;
                            f0 = (mp[0] != 0.0f); f1 = (mp[1] != 0.0f);
                        }
                    }
                    x0 = f0 ? sigf(x0) : 0.0f;
                    x1 = f1 ? sigf(x1) : 0.0f;
                }

                if (EPI == 2) {
                    float2 p; p.x = x0; p.y = x1;
                    *reinterpret_cast<float2*>(Of + (size_t)gr * ldo + gc) = p;
                } else {
                    __half2 ph = __halves2half2(__float2half_rn(x0),
                                                __float2half_rn(x1));
                    *reinterpret_cast<__half2*>(Oh + (size_t)gr * ldo + gc) = ph;
                }
            }
        }
}

// ---------------- kernels -----------------------------------------------------
template<int EPI, bool BTRANS>
__global__ void __launch_bounds__(256, 2)
gemm_fp16(const fp16* __restrict__ Ap, const fp16* __restrict__ Bp,
          fp16* __restrict__ Oh, float* __restrict__ Of,
          const float* __restrict__ bias, const void* __restrict__ mask,
          int lda, int ldb, int ldo, int K,
          long sA, long sB, long sO)
{
    extern __shared__ char smem[];
    gemm_body<EPI, BTRANS>(smem, smem_u32(smem),
                           Ap, Bp, Oh, Of, bias, mask,
                           lda, ldb, ldo, K, sA, sB, sO,
                           blockIdx.z, blockIdx.y * 128, blockIdx.x * 128);
}

// Fused q-proj (z==0) + v-proj (z==1); both EPI3 (bias, fp16 store).
__global__ void __launch_bounds__(256, 2)
proj_dual(const fp16* __restrict__ qin, const fp16* __restrict__ wq,
          fp16* __restrict__ qo, const float* __restrict__ bq,
          const fp16* __restrict__ vin, const fp16* __restrict__ wv,
          fp16* __restrict__ vo, const float* __restrict__ bv)
{
    extern __shared__ char smem[];
    const uint32_t sm0 = smem_u32(smem);
    const int mb = blockIdx.y * 128, nb = blockIdx.x * 128;
    if (blockIdx.z == 0)
        gemm_body<3, false>(smem, sm0, qin, wq, qo, nullptr, bq, nullptr,
                            Dn, Dn, Dn, Dn, 0, 0, 0, 0, mb, nb);
    else
        gemm_body<3, false>(smem, sm0, vin, wv, vo, nullptr, bv, nullptr,
                            Dn, Dn, Dn, Dn, 0, 0, 0, 0, mb, nb);
}

// ---------------- host side ---------------------------------------------------
extern "C" void kernel_launch(void* const* d_in, const int* in_sizes, int n_in,
                              void* d_out, int out_size)
{
    const float* queries = (const float*)d_in[0];
    const float* values  = (const float*)d_in[1];
    const void*  mask    = d_in[2];
    const float* Wq = (const float*)d_in[3];
    const float* bq = (const float*)d_in[4];
    const float* Wk = (const float*)d_in[5];
    const float* bk = (const float*)d_in[6];
    const float* Wv = (const float*)d_in[7];
    const float* bv = (const float*)d_in[8];
    float* out = (float*)d_out;

    fp16 *q, *k, *v, *at, *qin, *vin, *wq, *wk, *wv;
    cudaGetSymbolAddress((void**)&qin, g_qin);
    cudaGetSymbolAddress((void**)&vin, g_vin);
    cudaGetSymbolAddress((void**)&wq,  g_wq);
    cudaGetSymbolAddress((void**)&wk,  g_wk);
    cudaGetSymbolAddress((void**)&wv,  g_wv);
    cudaGetSymbolAddress((void**)&q,   g_q);
    cudaGetSymbolAddress((void**)&k,   g_k);
    cudaGetSymbolAddress((void**)&v,   g_v);
    cudaGetSymbolAddress((void**)&at,  g_at);

    constexpr int SMEM   = 3 * 32768;            // 96 KB
    constexpr int SMEM_M = 3 * 32768 + 16384;    // 112 KB (score: +mask tile)
    static int attr_done = 0;
    if (!attr_done) {
        cudaFuncSetAttribute(proj_dual,
                             cudaFuncAttributeMaxDynamicSharedMemorySize, SMEM);
        cudaFuncSetAttribute(gemm_fp16<3, false>,
                             cudaFuncAttributeMaxDynamicSharedMemorySize, SMEM);
        cudaFuncSetAttribute(gemm_fp16<1, false>,
                             cudaFuncAttributeMaxDynamicSharedMemorySize, SMEM_M);
        cudaFuncSetAttribute(gemm_fp16<2, true>,
                             cudaFuncAttributeMaxDynamicSharedMemorySize, SMEM);
        attr_done = 1;
    }

    // launch 1: mask dtype detection
    detect_mask_kernel<<<1, 256>>>((const unsigned*)mask, 8192);

    // launch 2: fused prep (pure fp16 converts)
    {
        const int N4 = MR * Dn / 4, W4 = Dn * Dn / 4;
        const int total = 2 * N4 + 3 * W4;
        prep_kernel<<<(total + 255) / 256, 256>>>(queries, values, Wq, Wk, Wv);
    }

    // launch 3: fused q-proj + v-proj
    proj_dual<<<dim3(6, 128, 2), 256, SMEM>>>(
        qin, wq, q, bq, vin, wv, v, bv);

    // launch 4: k = v @ Wk^T + bk
    gemm_fp16<3, false><<<dim3(6, 128, 1), 256, SMEM>>>(
        v, wk, k, nullptr, bk, nullptr,
        Dn, Dn, Dn, Dn, 0, 0, 0);

    // launch 5: score = sigmoid(mask ? q@k^T : -1e9), mask tile in smem
    gemm_fp16<1, false><<<dim3(16, 16, Bn), 256, SMEM_M>>>(
        q, k, at, nullptr, nullptr, mask,
        Dn, Dn, LKn, Dn,
        (long)LQn * Dn, (long)LKn * Dn, (long)LQn * LKn);

    // launch 6: out = attn @ v (NN)
    gemm_fp16<2, true><<<dim3(6, 16, Bn), 256, SMEM>>>(
        at, v, nullptr, out, nullptr, nullptr,
        LKn, Dn, Dn, LKn,
        (long)LQn * LKn, (long)LKn * Dn, (long)LQn * Dn);
}